// round 12
// baseline (speedup 1.0000x reference)
#include <cuda_runtime.h>
#include <cuda_fp16.h>
#include <cstdint>
#include <cstddef>

#define BATCH  4
#define S_LEN  2048
#define DMODEL 1024
#define NH     16
#define HDK    64
#define MROWS  (BATCH * S_LEN)   // 8192
#define MD     ((size_t)MROWS * DMODEL)
#define DD     ((size_t)DMODEL * DMODEL)

// ---------------- scratch (device globals; no runtime allocation) ----------
__device__ __half g_Ah[3 * MD];   // GEMM A hi (q,k,v inputs; slot 0 reused for ctx)
__device__ __half g_Al[3 * MD];   // GEMM A lo
__device__ __half g_Ph[3 * MD];   // Q,K,V in [B,H,S,DK], hi
__device__ __half g_Pl[3 * MD];   // lo
__device__ __half g_Wh[4 * DD];   // weight^T hi [N][K]
__device__ __half g_Wl[4 * DD];   // lo
__device__ uint32_t g_Mb[(size_t)BATCH * S_LEN * (S_LEN / 32)];  // bit mask

// ---------------- PTX helpers (family-portable) -----------------------------
__device__ __forceinline__ uint32_t smem_u32(const void* p) {
    uint32_t a;
    asm("{ .reg .u64 t; cvta.to.shared.u64 t, %1; cvt.u32.u64 %0, t; }"
        : "=r"(a) : "l"(p));
    return a;
}
__device__ __forceinline__ void ldsm_x4(uint32_t* r, uint32_t addr) {
    asm volatile("ldmatrix.sync.aligned.m8n8.x4.shared.b16 {%0,%1,%2,%3}, [%4];"
                 : "=r"(r[0]), "=r"(r[1]), "=r"(r[2]), "=r"(r[3]) : "r"(addr));
}
__device__ __forceinline__ void ldsm_x4t(uint32_t* r, uint32_t addr) {
    asm volatile("ldmatrix.sync.aligned.m8n8.x4.trans.shared.b16 {%0,%1,%2,%3}, [%4];"
                 : "=r"(r[0]), "=r"(r[1]), "=r"(r[2]), "=r"(r[3]) : "r"(addr));
}
__device__ __forceinline__ void ldsm_x2(uint32_t* r, uint32_t addr) {
    asm volatile("ldmatrix.sync.aligned.m8n8.x2.shared.b16 {%0,%1}, [%2];"
                 : "=r"(r[0]), "=r"(r[1]) : "r"(addr));
}
// fp16 operands, fp32 accumulate
__device__ __forceinline__ void mma16816(float* d, const uint32_t* a,
                                         const uint32_t* b) {
    asm volatile(
        "mma.sync.aligned.m16n8k16.row.col.f32.f16.f16.f32 "
        "{%0,%1,%2,%3}, {%4,%5,%6,%7}, {%8,%9}, {%0,%1,%2,%3};"
        : "+f"(d[0]), "+f"(d[1]), "+f"(d[2]), "+f"(d[3])
        : "r"(a[0]), "r"(a[1]), "r"(a[2]), "r"(a[3]), "r"(b[0]), "r"(b[1]));
}
__device__ __forceinline__ void cpa16(uint32_t dst, const void* src) {
    asm volatile("cp.async.cg.shared.global [%0], [%1], 16;"
                 :: "r"(dst), "l"(src) : "memory");
}
#define CP_COMMIT() asm volatile("cp.async.commit_group;" ::: "memory")
#define CP_WAIT(n)  asm volatile("cp.async.wait_group %0;" :: "n"(n) : "memory")

// pack two fp32 into fp16x2 hi, producing residual fp16x2 lo
__device__ __forceinline__ uint32_t pack_split(float a, float b, uint32_t& lo) {
    __half2 hh = __floats2half2_rn(a, b);
    float ra = a - __half2float(__low2half(hh));
    float rb = b - __half2float(__high2half(hh));
    __half2 ll = __floats2half2_rn(ra, rb);
    lo = *(uint32_t*)&ll;
    return *(uint32_t*)&hh;
}

// ---------------- fast exp2 (FMA-only) -------------------------------------
__device__ __forceinline__ float fexp2(float t) {
    t = fmaxf(t, -126.0f);
    float z  = t + 12582912.0f;
    int   ei = __float_as_int(z) - 0x4B400000;
    float f  = t - (z - 12582912.0f);
    float p  = 1.33335581e-3f;
    p = fmaf(p, f, 9.61812911e-3f);
    p = fmaf(p, f, 5.55041087e-2f);
    p = fmaf(p, f, 2.40226507e-1f);
    p = fmaf(p, f, 6.93147181e-1f);
    p = fmaf(p, f, 1.0f);
    return __int_as_float(__float_as_int(p) + (ei << 23));
}

// ============================================================================
// fused prep: grid (1024, 5). y=0..2: split q/k/v. y=3: transpose+split 4
// weights. y=4: bit-pack mask.
// ============================================================================
__global__ __launch_bounds__(256)
void prep(const float* __restrict__ q, const float* __restrict__ k,
          const float* __restrict__ v,
          const float* __restrict__ Wq, const float* __restrict__ Wk,
          const float* __restrict__ Wv, const float* __restrict__ Wo,
          const int* __restrict__ mask,
          __half* __restrict__ xh, __half* __restrict__ xl,
          __half* __restrict__ wh, __half* __restrict__ wl,
          uint32_t* __restrict__ bits)
{
    const int y   = blockIdx.y;
    const int bid = blockIdx.x;
    const int tid = threadIdx.x;

    if (y < 3) {
        const int n4 = (int)(MD / 4);
        const float* x = (y == 0) ? q : (y == 1) ? k : v;
        const size_t zo = (size_t)y * n4;
        int i = bid * 256 + tid;
        const int stride = 1024 * 256;
        for (; i < n4; i += stride) {
            float4 vv = ((const float4*)x)[i];
            uint2 H, L;
            H.x = pack_split(vv.x, vv.y, L.x);
            H.y = pack_split(vv.z, vv.w, L.y);
            ((uint2*)xh)[zo + i] = H;
            ((uint2*)xl)[zo + i] = L;
        }
    } else if (y == 3) {
        __shared__ float t[32][33];
        const int tx = tid & 31;
        const int ty = tid >> 5;
#pragma unroll
        for (int it = 0; it < 4; ++it) {
            const int z = it;
            const float* W = (z == 0) ? Wq : (z == 1) ? Wk : (z == 2) ? Wv : Wo;
            const size_t zo = (size_t)z * DD;
            const int n0 = (bid & 31) * 32;
            const int k0 = (bid >> 5) * 32;
#pragma unroll
            for (int i = ty; i < 32; i += 8)
                t[i][tx] = W[(size_t)(k0 + i) * DMODEL + n0 + tx];
            __syncthreads();
#pragma unroll
            for (int i = ty; i < 32; i += 8) {
                float vv = t[tx][i];
                __half h = __float2half_rn(vv);
                __half l = __float2half_rn(vv - __half2float(h));
                size_t o = zo + (size_t)(n0 + i) * DMODEL + k0 + tx;
                wh[o] = h;
                wl[o] = l;
            }
            __syncthreads();
        }
    } else {
        const size_t tot = (size_t)BATCH * S_LEN * S_LEN;
        size_t idx = (size_t)bid * 256 + tid;
        const size_t stride = (size_t)1024 * 256;
        for (; idx < tot; idx += stride) {
            int mv = mask[idx];
            uint32_t bal = __ballot_sync(0xffffffffu, mv != 0);
            if ((tid & 31) == 0) bits[idx >> 5] = bal;
        }
    }
}

// ============================================================================
// HMMA split-fp16 GEMM, BM=64, BN template (64|128), 3 CTAs/SM target,
// cp.async double-buffered, 3-pass fp32-accumulate.
// MODE 0: fp32 out row-major. MODE 1: fp16 hi/lo out in [B,H,S,DK], z-fused.
// Small tiles -> many equal work units -> wave-quantization ratio ~1.
// ============================================================================
template <int MODE, int BN>
__global__ __launch_bounds__(256, 3)
void gemm_mma(const __half* __restrict__ Ab_, const __half* __restrict__ Al_,
              const __half* __restrict__ Bh_, const __half* __restrict__ Bl_,
              const float* __restrict__ b0, const float* __restrict__ b1,
              const float* __restrict__ b2, float* __restrict__ C,
              __half* __restrict__ Ch_, __half* __restrict__ Cl_)
{
    constexpr int AEL = 64 * 40;            // A tile elems (padded stride 40)
    constexpr int BEL = BN * 40;            // B tile elems
    constexpr int OFF_AL = AEL * 2;         // bytes
    constexpr int OFF_BH = 2 * AEL * 2;
    constexpr int OFF_BL = OFF_BH + BEL * 2;
    constexpr int STG_B  = (2 * AEL + 2 * BEL) * 2;   // stage bytes
    constexpr int NJ = BN / 32;             // n-fragments per warp

    extern __shared__ __half smm[];
    const int tid  = threadIdx.x;
    const int lane = tid & 31;
    const int wid  = tid >> 5;
    const int wm   = wid >> 2;       // 0..1 (32 rows each)
    const int wn   = wid & 3;        // 0..3 (BN/4 cols each)
    const int bx   = blockIdx.x;     // N tile
    const int by   = blockIdx.y;     // M tile (128)
    const int z    = blockIdx.z;
    const uint32_t sbase = smem_u32(smm);

    const __half* Ah = Ab_ + (size_t)z * MD;
    const __half* Al = Al_ + (size_t)z * MD;
    const __half* Bh = Bh_ + (size_t)z * DD;
    const __half* Bl = Bl_ + (size_t)z * DD;
    const float* bias = (z == 0) ? b0 : (z == 1) ? b1 : b2;
    __half* Ch = Ch_ + (size_t)z * MD;
    __half* Cl = Cl_ + (size_t)z * MD;

    // loaders: A 64 rows x 32 cols: 4 thr/row, 8 elems; B likewise per BN
    const int lra = tid >> 2;            // 0..63
    const int lca = (tid & 3) * 8;
    const __half* pAh = Ah + (size_t)(by * 64 + lra) * DMODEL + lca;
    const __half* pAl = Al + (size_t)(by * 64 + lra) * DMODEL + lca;

    // B loader depends on BN: BN=64 -> 1 cpa16/matrix; BN=128 -> 2.
    const int lrb = (BN == 64) ? (tid >> 2) : (tid >> 1);
    const int lcb = (BN == 64) ? ((tid & 3) * 8) : ((tid & 1) * 16);
    const __half* pBh = Bh + (size_t)(bx * BN + lrb) * DMODEL + lcb;
    const __half* pBl = Bl + (size_t)(bx * BN + lrb) * DMODEL + lcb;

    auto copy_stage = [&](int kb, int s) {
        const int go = kb * 32;
        const uint32_t da = sbase + (uint32_t)(s * STG_B) + (uint32_t)(lra * 40 + lca) * 2;
        cpa16(da,          pAh + go);
        cpa16(da + OFF_AL, pAl + go);
        const uint32_t db = sbase + (uint32_t)(s * STG_B) + (uint32_t)(lrb * 40 + lcb) * 2;
        if (BN == 64) {
            cpa16(db + OFF_BH, pBh + go);
            cpa16(db + OFF_BL, pBl + go);
        } else {
            cpa16(db + OFF_BH,      pBh + go);
            cpa16(db + OFF_BH + 16, pBh + go + 8);
            cpa16(db + OFF_BL,      pBl + go);
            cpa16(db + OFF_BL + 16, pBl + go + 8);
        }
    };

    float acc[2][NJ][4];
#pragma unroll
    for (int i = 0; i < 2; ++i)
#pragma unroll
        for (int j = 0; j < NJ; ++j)
#pragma unroll
            for (int r = 0; r < 4; ++r) acc[i][j][r] = 0.0f;

    copy_stage(0, 0);
    CP_COMMIT();

    const int NKB = DMODEL / 32;
    for (int kb = 0; kb < NKB; ++kb) {
        const int cur = kb & 1;
        if (kb + 1 < NKB) {
            copy_stage(kb + 1, 1 - cur);
            CP_COMMIT();
            CP_WAIT(1);
        } else {
            CP_WAIT(0);
        }
        __syncthreads();

        const uint32_t st = sbase + (uint32_t)(cur * STG_B);
#pragma unroll
        for (int ks = 0; ks < 2; ++ks) {
            uint32_t af[2][4], bh[NJ][2], bl[NJ][2];
            const int ca = ks * 16 + (lane >> 4) * 8;
            const int cb = ks * 16 + ((lane >> 3) & 1) * 8;
#pragma unroll
            for (int nj = 0; nj < NJ; ++nj) {
                const int rb = wn * (BN / 4) + nj * 8 + (lane & 7);
                const uint32_t bd = st + OFF_BH + (uint32_t)(rb * 40 + cb) * 2;
                ldsm_x2(bh[nj], bd);
                ldsm_x2(bl[nj], bd + (OFF_BL - OFF_BH));
            }
            // af = A-hi: AhBh + AhBl
#pragma unroll
            for (int mi = 0; mi < 2; ++mi) {
                const int ra = wm * 32 + mi * 16 + (lane & 15);
                ldsm_x4(af[mi], st + (uint32_t)(ra * 40 + ca) * 2);
            }
#pragma unroll
            for (int mi = 0; mi < 2; ++mi)
#pragma unroll
                for (int nj = 0; nj < NJ; ++nj)
                    mma16816(acc[mi][nj], af[mi], bh[nj]);
#pragma unroll
            for (int mi = 0; mi < 2; ++mi)
#pragma unroll
                for (int nj = 0; nj < NJ; ++nj)
                    mma16816(acc[mi][nj], af[mi], bl[nj]);
            // af = A-lo: AlBh
#pragma unroll
            for (int mi = 0; mi < 2; ++mi) {
                const int ra = wm * 32 + mi * 16 + (lane & 15);
                ldsm_x4(af[mi], st + OFF_AL + (uint32_t)(ra * 40 + ca) * 2);
            }
#pragma unroll
            for (int mi = 0; mi < 2; ++mi)
#pragma unroll
                for (int nj = 0; nj < NJ; ++nj)
                    mma16816(acc[mi][nj], af[mi], bh[nj]);
        }
        __syncthreads();
    }

#pragma unroll
    for (int mi = 0; mi < 2; ++mi) {
        const int r0 = by * 64 + wm * 32 + mi * 16 + (lane >> 2);
#pragma unroll
        for (int nj = 0; nj < NJ; ++nj) {
            const int col = bx * BN + wn * (BN / 4) + nj * 8 + (lane & 3) * 2;
            const float2 bv = *(const float2*)(bias + col);
            float2 v0, v1;
            v0.x = acc[mi][nj][0] + bv.x;  v0.y = acc[mi][nj][1] + bv.y;
            v1.x = acc[mi][nj][2] + bv.x;  v1.y = acc[mi][nj][3] + bv.y;
            if (MODE == 1) {
                const int h  = col >> 6;
                const int dk = col & 63;
                const int b0i = r0 >> 11, s0r = r0 & (S_LEN - 1);
                const int r1 = r0 + 8;
                const int b1i = r1 >> 11, s1r = r1 & (S_LEN - 1);
                size_t i0 = (((size_t)b0i * NH + h) * S_LEN + s0r) * HDK + dk;
                size_t i1 = (((size_t)b1i * NH + h) * S_LEN + s1r) * HDK + dk;
                uint32_t l0, l1;
                uint32_t h0 = pack_split(v0.x, v0.y, l0);
                uint32_t h1 = pack_split(v1.x, v1.y, l1);
                *(uint32_t*)(Ch + i0) = h0;
                *(uint32_t*)(Cl + i0) = l0;
                *(uint32_t*)(Ch + i1) = h1;
                *(uint32_t*)(Cl + i1) = l1;
            } else {
                *(float2*)(C + (size_t)r0 * DMODEL + col) = v0;
                *(float2*)(C + (size_t)(r0 + 8) * DMODEL + col) = v1;
            }
        }
    }
}

// ============================================================================
// Flash attention, split-fp16 HMMA, cp.async double-buffered K/V pipeline.
// (unchanged — at the mma.sync floor)
// ============================================================================
#define AST 72                         // smem row stride in fp16 (64 + 8 pad)
#define KV_TILE_B (64 * AST * 2)       // 9216 bytes per 64x64 tile
#define STAGE_B   (4 * KV_TILE_B)      // 36864 bytes per stage (Kh,Kl,Vh,Vl)
#define ATT_SMEM  (2 * STAGE_B)        // 73728 bytes

__global__ __launch_bounds__(256, 2)
void attn_mma(void)
{
    extern __shared__ __half sma[];
    const int tid  = threadIdx.x;
    const int lane = tid & 31;
    const int w    = tid >> 5;
    const int h    = blockIdx.x;
    const int qt   = blockIdx.y;
    const int b    = blockIdx.z;
    const uint32_t sb = smem_u32(sma);

    const size_t headoff = ((size_t)b * NH + h) * S_LEN * HDK;
    const __half* Qhg = g_Ph + headoff + (size_t)qt * 128 * HDK;
    const __half* Qlg = g_Pl + headoff + (size_t)qt * 128 * HDK;
    const __half* Khg = g_Ph + MD + headoff;
    const __half* Klg = g_Pl + MD + headoff;
    const __half* Vhg = g_Ph + 2 * MD + headoff;
    const __half* Vlg = g_Pl + 2 * MD + headoff;

    auto copy_kv = [&](int kt, int s) {
        const int row = tid >> 2;
        const int c0  = (tid & 3) * 16;
        const size_t g = ((size_t)kt * 64 + row) * HDK + c0;
        const uint32_t d = sb + (uint32_t)(s * STAGE_B)
                         + (uint32_t)(row * AST + c0) * 2;
        cpa16(d,                  Khg + g);
        cpa16(d + 16,             Khg + g + 8);
        cpa16(d + KV_TILE_B,      Klg + g);
        cpa16(d + KV_TILE_B + 16, Klg + g + 8);
        cpa16(d + 2 * KV_TILE_B,      Vhg + g);
        cpa16(d + 2 * KV_TILE_B + 16, Vhg + g + 8);
        cpa16(d + 3 * KV_TILE_B,      Vlg + g);
        cpa16(d + 3 * KV_TILE_B + 16, Vlg + g + 8);
    };

    copy_kv(0, 0);
    CP_COMMIT();

    {   // Q (128x64 hi + lo) -> stage-1 region (plain stores, once)
        __half* Qs = sma + STAGE_B / 2;
        const int row = tid >> 1;
        const int c0  = (tid & 1) * 32;
#pragma unroll
        for (int i = 0; i < 4; ++i) {
            *(uint4*)(Qs + row * AST + c0 + i * 8) =
                *(const uint4*)(Qhg + (size_t)row * HDK + c0 + i * 8);
            *(uint4*)(Qs + 128 * AST + row * AST + c0 + i * 8) =
                *(const uint4*)(Qlg + (size_t)row * HDK + c0 + i * 8);
        }
    }
    __syncthreads();
    uint32_t qh[4][4], ql[4][4];
#pragma unroll
    for (int kc = 0; kc < 4; ++kc) {
        uint32_t ad = sb + STAGE_B
            + (uint32_t)((w * 16 + (lane & 15)) * AST + kc * 16 + (lane >> 4) * 8) * 2;
        ldsm_x4(qh[kc], ad);
        ldsm_x4(ql[kc], ad + 128 * AST * 2);
    }
    __syncthreads();

    float o[8][4];
#pragma unroll
    for (int i = 0; i < 8; ++i)
#pragma unroll
        for (int j = 0; j < 4; ++j) o[i][j] = 0.0f;
    float l0 = 0.0f, l1 = 0.0f;

    const float SC = 0.125f * 1.4426950408889634f;
    const int qrow0 = qt * 128 + w * 16 + (lane >> 2);
    const uint32_t* mb0 = g_Mb + ((size_t)b * S_LEN + qrow0) * (S_LEN / 32);
    const uint32_t* mb1 = mb0 + 8 * (S_LEN / 32);

    const int NKT = S_LEN / 64;
    for (int kt = 0; kt < NKT; ++kt) {
        const int cur = kt & 1;
        if (kt + 1 < NKT) {
            copy_kv(kt + 1, 1 - cur);
            CP_COMMIT();
            CP_WAIT(1);
        } else {
            CP_WAIT(0);
        }
        __syncthreads();

        const uint2 mu0 = *(const uint2*)(mb0 + 2 * kt);
        const uint2 mu1 = *(const uint2*)(mb1 + 2 * kt);

        const uint32_t st = sb + (uint32_t)(cur * STAGE_B);

        // ---- S = Q K^T (QhKh + QlKh + QhKl) ----
        float s[8][4];
#pragma unroll
        for (int i = 0; i < 8; ++i)
#pragma unroll
            for (int j = 0; j < 4; ++j) s[i][j] = 0.0f;

#pragma unroll
        for (int kc2 = 0; kc2 < 2; ++kc2) {
#pragma unroll
            for (int nj = 0; nj < 8; ++nj) {
                uint32_t bh[4], bl[4];
                uint32_t ad = st + (uint32_t)((nj * 8 + (lane & 7)) * AST
                                  + kc2 * 32 + (lane >> 3) * 8) * 2;
                ldsm_x4(bh, ad);
                ldsm_x4(bl, ad + KV_TILE_B);
                mma16816(s[nj], qh[2 * kc2],     bh);
                mma16816(s[nj], qh[2 * kc2 + 1], bh + 2);
                mma16816(s[nj], ql[2 * kc2],     bh);
                mma16816(s[nj], ql[2 * kc2 + 1], bh + 2);
                mma16816(s[nj], qh[2 * kc2],     bl);
                mma16816(s[nj], qh[2 * kc2 + 1], bl + 2);
            }
        }

        // ---- mask + scale + exp2 + local row sums ----
        float rs0 = 0.0f, rs1 = 0.0f;
        if ((mu0.x & mu0.y & mu1.x & mu1.y) == 0xffffffffu) {
#pragma unroll
            for (int nj = 0; nj < 8; ++nj) {
                s[nj][0] = fexp2(s[nj][0] * SC);
                s[nj][1] = fexp2(s[nj][1] * SC);
                s[nj][2] = fexp2(s[nj][2] * SC);
                s[nj][3] = fexp2(s[nj][3] * SC);
                rs0 += s[nj][0] + s[nj][1];
                rs1 += s[nj][2] + s[nj][3];
            }
        } else {
#pragma unroll
            for (int nj = 0; nj < 8; ++nj) {
                const uint32_t w0 = (nj < 4) ? mu0.x : mu0.y;
                const uint32_t w1 = (nj < 4) ? mu1.x : mu1.y;
                const int bit = (nj & 3) * 8 + (lane & 3) * 2;
                s[nj][0] = ((w0 >> bit) & 1u)       ? s[nj][0] * SC : -1e9f;
                s[nj][1] = ((w0 >> (bit + 1)) & 1u) ? s[nj][1] * SC : -1e9f;
                s[nj][2] = ((w1 >> bit) & 1u)       ? s[nj][2] * SC : -1e9f;
                s[nj][3] = ((w1 >> (bit + 1)) & 1u) ? s[nj][3] * SC : -1e9f;
                s[nj][0] = fexp2(s[nj][0]);
                s[nj][1] = fexp2(s[nj][1]);
                s[nj][2] = fexp2(s[nj][2]);
                s[nj][3] = fexp2(s[nj][3]);
                rs0 += s[nj][0] + s[nj][1];
                rs1 += s[nj][2] + s[nj][3];
            }
        }
        l0 += rs0;
        l1 += rs1;

        // ---- pack ALL of P to fp16 hi/lo ----
        uint32_t ph[16], pl[16];
#pragma unroll
        for (int nj = 0; nj < 8; ++nj) {
            ph[nj * 2]     = pack_split(s[nj][0], s[nj][1], pl[nj * 2]);
            ph[nj * 2 + 1] = pack_split(s[nj][2], s[nj][3], pl[nj * 2 + 1]);
        }

        // ---- O += P V (PhVh + PlVh + PhVl) ----
#pragma unroll
        for (int kc2 = 0; kc2 < 2; ++kc2) {
            const uint32_t* phA = ph + kc2 * 8;
            const uint32_t* plA = pl + kc2 * 8;
#pragma unroll
            for (int nj2 = 0; nj2 < 8; ++nj2) {
                uint32_t vh[4], vl[4];
                uint32_t ad = st + 2 * KV_TILE_B
                    + (uint32_t)((kc2 * 32 + lane) * AST + nj2 * 8) * 2;
                ldsm_x4t(vh, ad);
                ldsm_x4t(vl, ad + KV_TILE_B);
                mma16816(o[nj2], phA,     vh);
                mma16816(o[nj2], phA + 4, vh + 2);
                mma16816(o[nj2], plA,     vh);
                mma16816(o[nj2], plA + 4, vh + 2);
                mma16816(o[nj2], phA,     vl);
                mma16816(o[nj2], phA + 4, vl + 2);
            }
        }
        __syncthreads();
    }

    // ---- reduce row sums once, normalize, write ctx hi/lo ----
    l0 += __shfl_xor_sync(0xffffffffu, l0, 1);
    l0 += __shfl_xor_sync(0xffffffffu, l0, 2);
    l1 += __shfl_xor_sync(0xffffffffu, l1, 1);
    l1 += __shfl_xor_sync(0xffffffffu, l1, 2);
    const float inv0 = 1.0f / l0;
    const float inv1 = 1.0f / l1;
    const size_t base0 = ((size_t)b * S_LEN + qrow0) * DMODEL
                         + h * HDK + (lane & 3) * 2;
    const size_t base1 = base0 + (size_t)8 * DMODEL;
#pragma unroll
    for (int nj2 = 0; nj2 < 8; ++nj2) {
        uint32_t lo0, lo1;
        uint32_t hi0 = pack_split(o[nj2][0] * inv0, o[nj2][1] * inv0, lo0);
        uint32_t hi1 = pack_split(o[nj2][2] * inv1, o[nj2][3] * inv1, lo1);
        *(uint32_t*)(g_Ah + base0 + nj2 * 8) = hi0;
        *(uint32_t*)(g_Al + base0 + nj2 * 8) = lo0;
        *(uint32_t*)(g_Ah + base1 + nj2 * 8) = hi1;
        *(uint32_t*)(g_Al + base1 + nj2 * 8) = lo1;
    }
}

// ---------------- launch ----------------------------------------------------
extern "C" void kernel_launch(void* const* d_in, const int* in_sizes, int n_in,
                              void* d_out, int out_size)
{
    (void)in_sizes; (void)n_in; (void)out_size;
    const float* q  = (const float*)d_in[0];
    const float* k  = (const float*)d_in[1];
    const float* v  = (const float*)d_in[2];
    const int*   mk = (const int*)  d_in[3];
    const float* Wq = (const float*)d_in[4];
    const float* bq = (const float*)d_in[5];
    const float* Wk = (const float*)d_in[6];
    const float* bk = (const float*)d_in[7];
    const float* Wv = (const float*)d_in[8];
    const float* bv = (const float*)d_in[9];
    const float* Wo = (const float*)d_in[10];
    const float* bo = (const float*)d_in[11];
    float* out = (float*)d_out;

    __half *pAh, *pAl, *pPh, *pPl, *pWh, *pWl;
    uint32_t* pMb;
    cudaGetSymbolAddress((void**)&pAh, g_Ah);
    cudaGetSymbolAddress((void**)&pAl, g_Al);
    cudaGetSymbolAddress((void**)&pPh, g_Ph);
    cudaGetSymbolAddress((void**)&pPl, g_Pl);
    cudaGetSymbolAddress((void**)&pWh, g_Wh);
    cudaGetSymbolAddress((void**)&pWl, g_Wl);
    cudaGetSymbolAddress((void**)&pMb, g_Mb);

    // stage bytes: BN128 -> 30720*2; BN64 -> 20480*2
    const int SM128 = 2 * (2 * 64 * 40 + 2 * 128 * 40) * 2;  // 61440
    const int SM64  = 2 * (2 * 64 * 40 + 2 * 64 * 40) * 2;   // 40960

    cudaFuncSetAttribute((const void*)gemm_mma<1, 128>,
                         cudaFuncAttributeMaxDynamicSharedMemorySize, SM128);
    cudaFuncSetAttribute((const void*)gemm_mma<0, 64>,
                         cudaFuncAttributeMaxDynamicSharedMemorySize, SM64);
    cudaFuncSetAttribute(attn_mma, cudaFuncAttributeMaxDynamicSharedMemorySize, ATT_SMEM);

    // fused prep
    prep<<<dim3(1024, 5), 256>>>(q, k, v, Wq, Wk, Wv, Wo, mk,
                                 pAh, pAl, pWh, pWl, pMb);
    // fused Q/K/V projections: BM=64, BN=128 -> 8 x 128 x 3 = 3072 units
    gemm_mma<1, 128><<<dim3(8, 128, 3), 256, SM128>>>(pAh, pAl, pWh, pWl,
                                                      bq, bk, bv, nullptr, pPh, pPl);
    // attention
    attn_mma<<<dim3(NH, S_LEN / 128, BATCH), 256, ATT_SMEM>>>();
    // output projection: BM=64, BN=64 -> 16 x 128 = 2048 units
    gemm_mma<0, 64><<<dim3(16, 128, 1), 256, SM64>>>(pAh, pAl, pWh + 3 * DD, pWl + 3 * DD,
                                                     bo, bo, bo, out, nullptr, nullptr);
}

// round 13
// speedup vs baseline: 1.0172x; 1.0172x over previous
#include <cuda_runtime.h>
#include <cuda_fp16.h>
#include <cstdint>
#include <cstddef>

#define BATCH  4
#define S_LEN  2048
#define DMODEL 1024
#define NH     16
#define HDK    64
#define MROWS  (BATCH * S_LEN)   // 8192
#define MD     ((size_t)MROWS * DMODEL)
#define DD     ((size_t)DMODEL * DMODEL)

// ---------------- scratch (device globals; no runtime allocation) ----------
__device__ __half g_Ah[3 * MD];   // GEMM A hi (q,k,v inputs; slot 0 reused for ctx)
__device__ __half g_Al[3 * MD];   // GEMM A lo
__device__ __half g_Ph[3 * MD];   // Q,K,V in [B,H,S,DK], hi (Q pre-scaled by SC)
__device__ __half g_Pl[3 * MD];   // lo
__device__ __half g_Wh[4 * DD];   // weight^T hi [N][K]
__device__ __half g_Wl[4 * DD];   // lo
__device__ uint32_t g_Mb[(size_t)BATCH * S_LEN * (S_LEN / 32)];  // bit mask

// ---------------- PTX helpers (family-portable) -----------------------------
__device__ __forceinline__ uint32_t smem_u32(const void* p) {
    uint32_t a;
    asm("{ .reg .u64 t; cvta.to.shared.u64 t, %1; cvt.u32.u64 %0, t; }"
        : "=r"(a) : "l"(p));
    return a;
}
__device__ __forceinline__ void ldsm_x4(uint32_t* r, uint32_t addr) {
    asm volatile("ldmatrix.sync.aligned.m8n8.x4.shared.b16 {%0,%1,%2,%3}, [%4];"
                 : "=r"(r[0]), "=r"(r[1]), "=r"(r[2]), "=r"(r[3]) : "r"(addr));
}
__device__ __forceinline__ void ldsm_x4t(uint32_t* r, uint32_t addr) {
    asm volatile("ldmatrix.sync.aligned.m8n8.x4.trans.shared.b16 {%0,%1,%2,%3}, [%4];"
                 : "=r"(r[0]), "=r"(r[1]), "=r"(r[2]), "=r"(r[3]) : "r"(addr));
}
__device__ __forceinline__ void ldsm_x2(uint32_t* r, uint32_t addr) {
    asm volatile("ldmatrix.sync.aligned.m8n8.x2.shared.b16 {%0,%1}, [%2];"
                 : "=r"(r[0]), "=r"(r[1]) : "r"(addr));
}
// fp16 operands, fp32 accumulate
__device__ __forceinline__ void mma16816(float* d, const uint32_t* a,
                                         const uint32_t* b) {
    asm volatile(
        "mma.sync.aligned.m16n8k16.row.col.f32.f16.f16.f32 "
        "{%0,%1,%2,%3}, {%4,%5,%6,%7}, {%8,%9}, {%0,%1,%2,%3};"
        : "+f"(d[0]), "+f"(d[1]), "+f"(d[2]), "+f"(d[3])
        : "r"(a[0]), "r"(a[1]), "r"(a[2]), "r"(a[3]), "r"(b[0]), "r"(b[1]));
}
__device__ __forceinline__ void cpa16(uint32_t dst, const void* src) {
    asm volatile("cp.async.cg.shared.global [%0], [%1], 16;"
                 :: "r"(dst), "l"(src) : "memory");
}
#define CP_COMMIT() asm volatile("cp.async.commit_group;" ::: "memory")
#define CP_WAIT(n)  asm volatile("cp.async.wait_group %0;" :: "n"(n) : "memory")

// pack two fp32 into fp16x2 hi, producing residual fp16x2 lo
__device__ __forceinline__ uint32_t pack_split(float a, float b, uint32_t& lo) {
    __half2 hh = __floats2half2_rn(a, b);
    float ra = a - __half2float(__low2half(hh));
    float rb = b - __half2float(__high2half(hh));
    __half2 ll = __floats2half2_rn(ra, rb);
    lo = *(uint32_t*)&ll;
    return *(uint32_t*)&hh;
}

// ---------------- fast exp2 (FMA-only) -------------------------------------
__device__ __forceinline__ float fexp2(float t) {
    t = fmaxf(t, -126.0f);
    float z  = t + 12582912.0f;
    int   ei = __float_as_int(z) - 0x4B400000;
    float f  = t - (z - 12582912.0f);
    float p  = 1.33335581e-3f;
    p = fmaf(p, f, 9.61812911e-3f);
    p = fmaf(p, f, 5.55041087e-2f);
    p = fmaf(p, f, 2.40226507e-1f);
    p = fmaf(p, f, 6.93147181e-1f);
    p = fmaf(p, f, 1.0f);
    return __int_as_float(__float_as_int(p) + (ei << 23));
}

// ============================================================================
// fused prep: grid (1024, 5). y=0..2: split q/k/v. y=3: transpose+split 4
// weights. y=4: bit-pack mask.
// ============================================================================
__global__ __launch_bounds__(256)
void prep(const float* __restrict__ q, const float* __restrict__ k,
          const float* __restrict__ v,
          const float* __restrict__ Wq, const float* __restrict__ Wk,
          const float* __restrict__ Wv, const float* __restrict__ Wo,
          const int* __restrict__ mask,
          __half* __restrict__ xh, __half* __restrict__ xl,
          __half* __restrict__ wh, __half* __restrict__ wl,
          uint32_t* __restrict__ bits)
{
    const int y   = blockIdx.y;
    const int bid = blockIdx.x;
    const int tid = threadIdx.x;

    if (y < 3) {
        const int n4 = (int)(MD / 4);
        const float* x = (y == 0) ? q : (y == 1) ? k : v;
        const size_t zo = (size_t)y * n4;
        int i = bid * 256 + tid;
        const int stride = 1024 * 256;
        for (; i < n4; i += stride) {
            float4 vv = ((const float4*)x)[i];
            uint2 H, L;
            H.x = pack_split(vv.x, vv.y, L.x);
            H.y = pack_split(vv.z, vv.w, L.y);
            ((uint2*)xh)[zo + i] = H;
            ((uint2*)xl)[zo + i] = L;
        }
    } else if (y == 3) {
        __shared__ float t[32][33];
        const int tx = tid & 31;
        const int ty = tid >> 5;
#pragma unroll
        for (int it = 0; it < 4; ++it) {
            const int z = it;
            const float* W = (z == 0) ? Wq : (z == 1) ? Wk : (z == 2) ? Wv : Wo;
            const size_t zo = (size_t)z * DD;
            const int n0 = (bid & 31) * 32;
            const int k0 = (bid >> 5) * 32;
#pragma unroll
            for (int i = ty; i < 32; i += 8)
                t[i][tx] = W[(size_t)(k0 + i) * DMODEL + n0 + tx];
            __syncthreads();
#pragma unroll
            for (int i = ty; i < 32; i += 8) {
                float vv = t[tx][i];
                __half h = __float2half_rn(vv);
                __half l = __float2half_rn(vv - __half2float(h));
                size_t o = zo + (size_t)(n0 + i) * DMODEL + k0 + tx;
                wh[o] = h;
                wl[o] = l;
            }
            __syncthreads();
        }
    } else {
        const size_t tot = (size_t)BATCH * S_LEN * S_LEN;
        size_t idx = (size_t)bid * 256 + tid;
        const size_t stride = (size_t)1024 * 256;
        for (; idx < tot; idx += stride) {
            int mv = mask[idx];
            uint32_t bal = __ballot_sync(0xffffffffu, mv != 0);
            if ((tid & 31) == 0) bits[idx >> 5] = bal;
        }
    }
}

// ============================================================================
// HMMA split-fp16 GEMM, BM=128 BN=128, 2 CTAs/SM, cp.async double-buffered,
// 3-pass fp32-accumulate (R9 configuration — measured at the mma.sync floor).
// MODE 0: fp32 out row-major. MODE 1: fp16 hi/lo out in [B,H,S,DK], z-fused;
//         z==0 (Q) output is pre-scaled by SC = 0.125*log2(e).
// ============================================================================
#define TILE_E 5120            // one 128x32 fp16 tile, padded stride 40
#define GM_SMEM (2 * 4 * TILE_E * 2)   // 81920 bytes

template <int MODE>
__global__ __launch_bounds__(256, 2)
void gemm_mma(const __half* __restrict__ Ab_, const __half* __restrict__ Al_,
              const __half* __restrict__ Bh_, const __half* __restrict__ Bl_,
              const float* __restrict__ b0, const float* __restrict__ b1,
              const float* __restrict__ b2, float* __restrict__ C,
              __half* __restrict__ Ch_, __half* __restrict__ Cl_)
{
    extern __shared__ __half smm[];
    const int tid  = threadIdx.x;
    const int lane = tid & 31;
    const int wid  = tid >> 5;
    const int wm   = wid >> 2;
    const int wn   = wid & 3;
    const int bx   = blockIdx.x;
    const int by   = blockIdx.y;
    const int z    = blockIdx.z;
    const uint32_t sbase = smem_u32(smm);

    const __half* Ah = Ab_ + (size_t)z * MD;
    const __half* Al = Al_ + (size_t)z * MD;
    const __half* Bh = Bh_ + (size_t)z * DD;
    const __half* Bl = Bl_ + (size_t)z * DD;
    const float* bias = (z == 0) ? b0 : (z == 1) ? b1 : b2;
    __half* Ch = Ch_ + (size_t)z * MD;
    __half* Cl = Cl_ + (size_t)z * MD;
    // Q (z==0) pre-scaled by SC so attention skips per-score multiply
    const float oscale = (MODE == 1 && z == 0) ? 0.18033688011112042f : 1.0f;

    const int lr = tid >> 1;
    const int lc = (tid & 1) * 16;
    const __half* pAh = Ah + (size_t)(by * 128 + lr) * DMODEL + lc;
    const __half* pAl = Al + (size_t)(by * 128 + lr) * DMODEL + lc;
    const __half* pBh = Bh + (size_t)(bx * 128 + lr) * DMODEL + lc;
    const __half* pBl = Bl + (size_t)(bx * 128 + lr) * DMODEL + lc;

    auto copy_stage = [&](int kb, int s) {
        const uint32_t d = sbase + (uint32_t)(s * 4 * TILE_E + lr * 40 + lc) * 2;
        const int go = kb * 32;
        cpa16(d,                    pAh + go);
        cpa16(d + 16,               pAh + go + 8);
        cpa16(d + TILE_E * 2,       pAl + go);
        cpa16(d + TILE_E * 2 + 16,  pAl + go + 8);
        cpa16(d + 4 * TILE_E,       pBh + go);
        cpa16(d + 4 * TILE_E + 16,  pBh + go + 8);
        cpa16(d + 6 * TILE_E,       pBl + go);
        cpa16(d + 6 * TILE_E + 16,  pBl + go + 8);
    };

    float acc[4][4][4];
#pragma unroll
    for (int i = 0; i < 4; ++i)
#pragma unroll
        for (int j = 0; j < 4; ++j)
#pragma unroll
            for (int r = 0; r < 4; ++r) acc[i][j][r] = 0.0f;

    copy_stage(0, 0);
    CP_COMMIT();

    const int NKB = DMODEL / 32;
    for (int kb = 0; kb < NKB; ++kb) {
        const int cur = kb & 1;
        if (kb + 1 < NKB) {
            copy_stage(kb + 1, 1 - cur);
            CP_COMMIT();
            CP_WAIT(1);
        } else {
            CP_WAIT(0);
        }
        __syncthreads();

        const uint32_t stA = sbase + (uint32_t)(cur * 4) * TILE_E * 2;
        const uint32_t stB = stA + 2u * TILE_E * 2;
#pragma unroll
        for (int ks = 0; ks < 2; ++ks) {
            uint32_t ah[4][4], al[4][4], bh[4][2], bl[4][2];
            const int ca = ks * 16 + (lane >> 4) * 8;
#pragma unroll
            for (int mi = 0; mi < 4; ++mi) {
                const int ra = wm * 64 + mi * 16 + (lane & 15);
                const uint32_t ad = stA + (uint32_t)(ra * 40 + ca) * 2;
                ldsm_x4(ah[mi], ad);
                ldsm_x4(al[mi], ad + TILE_E * 2);
            }
            const int cb = ks * 16 + ((lane >> 3) & 1) * 8;
#pragma unroll
            for (int nj = 0; nj < 4; ++nj) {
                const int rb = wn * 32 + nj * 8 + (lane & 7);
                const uint32_t bd = stB + (uint32_t)(rb * 40 + cb) * 2;
                ldsm_x2(bh[nj], bd);
                ldsm_x2(bl[nj], bd + TILE_E * 2);
            }
#pragma unroll
            for (int mi = 0; mi < 4; ++mi)
#pragma unroll
                for (int nj = 0; nj < 4; ++nj)
                    mma16816(acc[mi][nj], ah[mi], bh[nj]);
#pragma unroll
            for (int mi = 0; mi < 4; ++mi)
#pragma unroll
                for (int nj = 0; nj < 4; ++nj)
                    mma16816(acc[mi][nj], al[mi], bh[nj]);
#pragma unroll
            for (int mi = 0; mi < 4; ++mi)
#pragma unroll
                for (int nj = 0; nj < 4; ++nj)
                    mma16816(acc[mi][nj], ah[mi], bl[nj]);
        }
        __syncthreads();
    }

#pragma unroll
    for (int mi = 0; mi < 4; ++mi) {
        const int r0 = by * 128 + wm * 64 + mi * 16 + (lane >> 2);
#pragma unroll
        for (int nj = 0; nj < 4; ++nj) {
            const int col = bx * 128 + wn * 32 + nj * 8 + (lane & 3) * 2;
            const float2 bv = *(const float2*)(bias + col);
            float2 v0, v1;
            v0.x = (acc[mi][nj][0] + bv.x) * oscale;
            v0.y = (acc[mi][nj][1] + bv.y) * oscale;
            v1.x = (acc[mi][nj][2] + bv.x) * oscale;
            v1.y = (acc[mi][nj][3] + bv.y) * oscale;
            if (MODE == 1) {
                const int h  = col >> 6;
                const int dk = col & 63;
                const int b0i = r0 >> 11, s0r = r0 & (S_LEN - 1);
                const int r1 = r0 + 8;
                const int b1i = r1 >> 11, s1r = r1 & (S_LEN - 1);
                size_t i0 = (((size_t)b0i * NH + h) * S_LEN + s0r) * HDK + dk;
                size_t i1 = (((size_t)b1i * NH + h) * S_LEN + s1r) * HDK + dk;
                uint32_t l0, l1;
                uint32_t h0 = pack_split(v0.x, v0.y, l0);
                uint32_t h1 = pack_split(v1.x, v1.y, l1);
                *(uint32_t*)(Ch + i0) = h0;
                *(uint32_t*)(Cl + i0) = l0;
                *(uint32_t*)(Ch + i1) = h1;
                *(uint32_t*)(Cl + i1) = l1;
            } else {
                *(float2*)(C + (size_t)r0 * DMODEL + col) = v0;
                *(float2*)(C + (size_t)(r0 + 8) * DMODEL + col) = v1;
            }
        }
    }
}

// ============================================================================
// Flash attention, split-fp16 HMMA, cp.async double-buffered K/V pipeline.
// Q pre-scaled by SC at projection; scores go straight into exp2.
// ============================================================================
#define AST 72                         // smem row stride in fp16 (64 + 8 pad)
#define KV_TILE_B (64 * AST * 2)       // 9216 bytes per 64x64 tile
#define STAGE_B   (4 * KV_TILE_B)      // 36864 bytes per stage (Kh,Kl,Vh,Vl)
#define ATT_SMEM  (2 * STAGE_B)        // 73728 bytes

__global__ __launch_bounds__(256, 2)
void attn_mma(void)
{
    extern __shared__ __half sma[];
    const int tid  = threadIdx.x;
    const int lane = tid & 31;
    const int w    = tid >> 5;
    const int h    = blockIdx.x;
    const int qt   = blockIdx.y;
    const int b    = blockIdx.z;
    const uint32_t sb = smem_u32(sma);

    const size_t headoff = ((size_t)b * NH + h) * S_LEN * HDK;
    const __half* Qhg = g_Ph + headoff + (size_t)qt * 128 * HDK;
    const __half* Qlg = g_Pl + headoff + (size_t)qt * 128 * HDK;
    const __half* Khg = g_Ph + MD + headoff;
    const __half* Klg = g_Pl + MD + headoff;
    const __half* Vhg = g_Ph + 2 * MD + headoff;
    const __half* Vlg = g_Pl + 2 * MD + headoff;

    auto copy_kv = [&](int kt, int s) {
        const int row = tid >> 2;
        const int c0  = (tid & 3) * 16;
        const size_t g = ((size_t)kt * 64 + row) * HDK + c0;
        const uint32_t d = sb + (uint32_t)(s * STAGE_B)
                         + (uint32_t)(row * AST + c0) * 2;
        cpa16(d,                  Khg + g);
        cpa16(d + 16,             Khg + g + 8);
        cpa16(d + KV_TILE_B,      Klg + g);
        cpa16(d + KV_TILE_B + 16, Klg + g + 8);
        cpa16(d + 2 * KV_TILE_B,      Vhg + g);
        cpa16(d + 2 * KV_TILE_B + 16, Vhg + g + 8);
        cpa16(d + 3 * KV_TILE_B,      Vlg + g);
        cpa16(d + 3 * KV_TILE_B + 16, Vlg + g + 8);
    };

    copy_kv(0, 0);
    CP_COMMIT();

    {   // Q (128x64 hi + lo) -> stage-1 region (plain stores, once)
        __half* Qs = sma + STAGE_B / 2;
        const int row = tid >> 1;
        const int c0  = (tid & 1) * 32;
#pragma unroll
        for (int i = 0; i < 4; ++i) {
            *(uint4*)(Qs + row * AST + c0 + i * 8) =
                *(const uint4*)(Qhg + (size_t)row * HDK + c0 + i * 8);
            *(uint4*)(Qs + 128 * AST + row * AST + c0 + i * 8) =
                *(const uint4*)(Qlg + (size_t)row * HDK + c0 + i * 8);
        }
    }
    __syncthreads();
    uint32_t qh[4][4], ql[4][4];
#pragma unroll
    for (int kc = 0; kc < 4; ++kc) {
        uint32_t ad = sb + STAGE_B
            + (uint32_t)((w * 16 + (lane & 15)) * AST + kc * 16 + (lane >> 4) * 8) * 2;
        ldsm_x4(qh[kc], ad);
        ldsm_x4(ql[kc], ad + 128 * AST * 2);
    }
    __syncthreads();

    float o[8][4];
#pragma unroll
    for (int i = 0; i < 8; ++i)
#pragma unroll
        for (int j = 0; j < 4; ++j) o[i][j] = 0.0f;
    float l0 = 0.0f, l1 = 0.0f;

    const int qrow0 = qt * 128 + w * 16 + (lane >> 2);
    const uint32_t* mb0 = g_Mb + ((size_t)b * S_LEN + qrow0) * (S_LEN / 32);
    const uint32_t* mb1 = mb0 + 8 * (S_LEN / 32);

    const int NKT = S_LEN / 64;
    for (int kt = 0; kt < NKT; ++kt) {
        const int cur = kt & 1;
        if (kt + 1 < NKT) {
            copy_kv(kt + 1, 1 - cur);
            CP_COMMIT();
            CP_WAIT(1);
        } else {
            CP_WAIT(0);
        }
        __syncthreads();

        const uint2 mu0 = *(const uint2*)(mb0 + 2 * kt);
        const uint2 mu1 = *(const uint2*)(mb1 + 2 * kt);

        const uint32_t st = sb + (uint32_t)(cur * STAGE_B);

        // ---- S = Q K^T (QhKh + QlKh + QhKl); Q pre-scaled by SC ----
        float s[8][4];
#pragma unroll
        for (int i = 0; i < 8; ++i)
#pragma unroll
            for (int j = 0; j < 4; ++j) s[i][j] = 0.0f;

#pragma unroll
        for (int kc2 = 0; kc2 < 2; ++kc2) {
#pragma unroll
            for (int nj = 0; nj < 8; ++nj) {
                uint32_t bh[4], bl[4];
                uint32_t ad = st + (uint32_t)((nj * 8 + (lane & 7)) * AST
                                  + kc2 * 32 + (lane >> 3) * 8) * 2;
                ldsm_x4(bh, ad);
                ldsm_x4(bl, ad + KV_TILE_B);
                mma16816(s[nj], qh[2 * kc2],     bh);
                mma16816(s[nj], qh[2 * kc2 + 1], bh + 2);
                mma16816(s[nj], ql[2 * kc2],     bh);
                mma16816(s[nj], ql[2 * kc2 + 1], bh + 2);
                mma16816(s[nj], qh[2 * kc2],     bl);
                mma16816(s[nj], qh[2 * kc2 + 1], bl + 2);
            }
        }

        // ---- mask + exp2 + local row sums (scores already in log2 units) ----
        float rs0 = 0.0f, rs1 = 0.0f;
        if ((mu0.x & mu0.y & mu1.x & mu1.y) == 0xffffffffu) {
#pragma unroll
            for (int nj = 0; nj < 8; ++nj) {
                s[nj][0] = fexp2(s[nj][0]);
                s[nj][1] = fexp2(s[nj][1]);
                s[nj][2] = fexp2(s[nj][2]);
                s[nj][3] = fexp2(s[nj][3]);
                rs0 += s[nj][0] + s[nj][1];
                rs1 += s[nj][2] + s[nj][3];
            }
        } else {
#pragma unroll
            for (int nj = 0; nj < 8; ++nj) {
                const uint32_t w0 = (nj < 4) ? mu0.x : mu0.y;
                const uint32_t w1 = (nj < 4) ? mu1.x : mu1.y;
                const int bit = (nj & 3) * 8 + (lane & 3) * 2;
                s[nj][0] = ((w0 >> bit) & 1u)       ? s[nj][0] : -1e9f;
                s[nj][1] = ((w0 >> (bit + 1)) & 1u) ? s[nj][1] : -1e9f;
                s[nj][2] = ((w1 >> bit) & 1u)       ? s[nj][2] : -1e9f;
                s[nj][3] = ((w1 >> (bit + 1)) & 1u) ? s[nj][3] : -1e9f;
                s[nj][0] = fexp2(s[nj][0]);
                s[nj][1] = fexp2(s[nj][1]);
                s[nj][2] = fexp2(s[nj][2]);
                s[nj][3] = fexp2(s[nj][3]);
                rs0 += s[nj][0] + s[nj][1];
                rs1 += s[nj][2] + s[nj][3];
            }
        }
        l0 += rs0;
        l1 += rs1;

        // ---- pack ALL of P to fp16 hi/lo ----
        uint32_t ph[16], pl[16];
#pragma unroll
        for (int nj = 0; nj < 8; ++nj) {
            ph[nj * 2]     = pack_split(s[nj][0], s[nj][1], pl[nj * 2]);
            ph[nj * 2 + 1] = pack_split(s[nj][2], s[nj][3], pl[nj * 2 + 1]);
        }

        // ---- O += P V (PhVh + PlVh + PhVl) ----
#pragma unroll
        for (int kc2 = 0; kc2 < 2; ++kc2) {
            const uint32_t* phA = ph + kc2 * 8;
            const uint32_t* plA = pl + kc2 * 8;
#pragma unroll
            for (int nj2 = 0; nj2 < 8; ++nj2) {
                uint32_t vh[4], vl[4];
                uint32_t ad = st + 2 * KV_TILE_B
                    + (uint32_t)((kc2 * 32 + lane) * AST + nj2 * 8) * 2;
                ldsm_x4t(vh, ad);
                ldsm_x4t(vl, ad + KV_TILE_B);
                mma16816(o[nj2], phA,     vh);
                mma16816(o[nj2], phA + 4, vh + 2);
                mma16816(o[nj2], plA,     vh);
                mma16816(o[nj2], plA + 4, vh + 2);
                mma16816(o[nj2], phA,     vl);
                mma16816(o[nj2], phA + 4, vl + 2);
            }
        }
        __syncthreads();
    }

    // ---- reduce row sums once, normalize, write ctx hi/lo ----
    l0 += __shfl_xor_sync(0xffffffffu, l0, 1);
    l0 += __shfl_xor_sync(0xffffffffu, l0, 2);
    l1 += __shfl_xor_sync(0xffffffffu, l1, 1);
    l1 += __shfl_xor_sync(0xffffffffu, l1, 2);
    const float inv0 = 1.0f / l0;
    const float inv1 = 1.0f / l1;
    const size_t base0 = ((size_t)b * S_LEN + qrow0) * DMODEL
                         + h * HDK + (lane & 3) * 2;
    const size_t base1 = base0 + (size_t)8 * DMODEL;
#pragma unroll
    for (int nj2 = 0; nj2 < 8; ++nj2) {
        uint32_t lo0, lo1;
        uint32_t hi0 = pack_split(o[nj2][0] * inv0, o[nj2][1] * inv0, lo0);
        uint32_t hi1 = pack_split(o[nj2][2] * inv1, o[nj2][3] * inv1, lo1);
        *(uint32_t*)(g_Ah + base0 + nj2 * 8) = hi0;
        *(uint32_t*)(g_Al + base0 + nj2 * 8) = lo0;
        *(uint32_t*)(g_Ah + base1 + nj2 * 8) = hi1;
        *(uint32_t*)(g_Al + base1 + nj2 * 8) = lo1;
    }
}

// ---------------- launch ----------------------------------------------------
extern "C" void kernel_launch(void* const* d_in, const int* in_sizes, int n_in,
                              void* d_out, int out_size)
{
    (void)in_sizes; (void)n_in; (void)out_size;
    const float* q  = (const float*)d_in[0];
    const float* k  = (const float*)d_in[1];
    const float* v  = (const float*)d_in[2];
    const int*   mk = (const int*)  d_in[3];
    const float* Wq = (const float*)d_in[4];
    const float* bq = (const float*)d_in[5];
    const float* Wk = (const float*)d_in[6];
    const float* bk = (const float*)d_in[7];
    const float* Wv = (const float*)d_in[8];
    const float* bv = (const float*)d_in[9];
    const float* Wo = (const float*)d_in[10];
    const float* bo = (const float*)d_in[11];
    float* out = (float*)d_out;

    __half *pAh, *pAl, *pPh, *pPl, *pWh, *pWl;
    uint32_t* pMb;
    cudaGetSymbolAddress((void**)&pAh, g_Ah);
    cudaGetSymbolAddress((void**)&pAl, g_Al);
    cudaGetSymbolAddress((void**)&pPh, g_Ph);
    cudaGetSymbolAddress((void**)&pPl, g_Pl);
    cudaGetSymbolAddress((void**)&pWh, g_Wh);
    cudaGetSymbolAddress((void**)&pWl, g_Wl);
    cudaGetSymbolAddress((void**)&pMb, g_Mb);

    cudaFuncSetAttribute(gemm_mma<0>, cudaFuncAttributeMaxDynamicSharedMemorySize, GM_SMEM);
    cudaFuncSetAttribute(gemm_mma<1>, cudaFuncAttributeMaxDynamicSharedMemorySize, GM_SMEM);
    cudaFuncSetAttribute(attn_mma,    cudaFuncAttributeMaxDynamicSharedMemorySize, ATT_SMEM);

    // fused prep: activation splits (y=0..2), weight splits (y=3), mask (y=4)
    prep<<<dim3(1024, 5), 256>>>(q, k, v, Wq, Wk, Wv, Wo, mk,
                                 pAh, pAl, pWh, pWl, pMb);
    // fused Q/K/V projections (Q epilogue pre-scales by SC)
    gemm_mma<1><<<dim3(8, 64, 3), 256, GM_SMEM>>>(pAh, pAl, pWh, pWl,
                                                  bq, bk, bv, nullptr, pPh, pPl);
    // attention (writes ctx hi/lo into g_Ah/g_Al slot 0)
    attn_mma<<<dim3(NH, S_LEN / 128, BATCH), 256, ATT_SMEM>>>();
    // output projection (weight slot 3)
    gemm_mma<0><<<dim3(8, 64, 1), 256, GM_SMEM>>>(pAh, pAl, pWh + 3 * DD, pWl + 3 * DD,
                                                  bo, bo, bo, out, nullptr, nullptr);
}

// round 14
// speedup vs baseline: 1.1615x; 1.1418x over previous
#include <cuda_runtime.h>
#include <cuda_fp16.h>
#include <cstdint>
#include <cstddef>

#define BATCH  4
#define S_LEN  2048
#define DMODEL 1024
#define NH     16
#define HDK    64
#define MROWS  (BATCH * S_LEN)   // 8192
#define MD     ((size_t)MROWS * DMODEL)
#define DD     ((size_t)DMODEL * DMODEL)

// ---------------- scratch (device globals; no runtime allocation) ----------
__device__ __half g_Ah[3 * MD];   // GEMM A hi (q,k,v inputs; slot 0 reused for ctx)
__device__ __half g_Al[3 * MD];   // GEMM A lo
__device__ __half g_Ph[3 * MD];   // Q,K,V in [B,H,S,DK], hi (Q pre-scaled by SC)
__device__ __half g_Pl[3 * MD];   // lo (attn reads only Q's lo)
__device__ __half g_Wh[4 * DD];   // weight^T hi [N][K]
__device__ __half g_Wl[4 * DD];   // lo
__device__ uint32_t g_Mb[(size_t)BATCH * S_LEN * (S_LEN / 32)];  // bit mask

// ---------------- PTX helpers (family-portable) -----------------------------
__device__ __forceinline__ uint32_t smem_u32(const void* p) {
    uint32_t a;
    asm("{ .reg .u64 t; cvta.to.shared.u64 t, %1; cvt.u32.u64 %0, t; }"
        : "=r"(a) : "l"(p));
    return a;
}
__device__ __forceinline__ void ldsm_x4(uint32_t* r, uint32_t addr) {
    asm volatile("ldmatrix.sync.aligned.m8n8.x4.shared.b16 {%0,%1,%2,%3}, [%4];"
                 : "=r"(r[0]), "=r"(r[1]), "=r"(r[2]), "=r"(r[3]) : "r"(addr));
}
__device__ __forceinline__ void ldsm_x4t(uint32_t* r, uint32_t addr) {
    asm volatile("ldmatrix.sync.aligned.m8n8.x4.trans.shared.b16 {%0,%1,%2,%3}, [%4];"
                 : "=r"(r[0]), "=r"(r[1]), "=r"(r[2]), "=r"(r[3]) : "r"(addr));
}
__device__ __forceinline__ void ldsm_x2(uint32_t* r, uint32_t addr) {
    asm volatile("ldmatrix.sync.aligned.m8n8.x2.shared.b16 {%0,%1}, [%2];"
                 : "=r"(r[0]), "=r"(r[1]) : "r"(addr));
}
// fp16 operands, fp32 accumulate
__device__ __forceinline__ void mma16816(float* d, const uint32_t* a,
                                         const uint32_t* b) {
    asm volatile(
        "mma.sync.aligned.m16n8k16.row.col.f32.f16.f16.f32 "
        "{%0,%1,%2,%3}, {%4,%5,%6,%7}, {%8,%9}, {%0,%1,%2,%3};"
        : "+f"(d[0]), "+f"(d[1]), "+f"(d[2]), "+f"(d[3])
        : "r"(a[0]), "r"(a[1]), "r"(a[2]), "r"(a[3]), "r"(b[0]), "r"(b[1]));
}
__device__ __forceinline__ void cpa16(uint32_t dst, const void* src) {
    asm volatile("cp.async.cg.shared.global [%0], [%1], 16;"
                 :: "r"(dst), "l"(src) : "memory");
}
#define CP_COMMIT() asm volatile("cp.async.commit_group;" ::: "memory")
#define CP_WAIT(n)  asm volatile("cp.async.wait_group %0;" :: "n"(n) : "memory")

// pack two fp32 into fp16x2 hi, producing residual fp16x2 lo
__device__ __forceinline__ uint32_t pack_split(float a, float b, uint32_t& lo) {
    __half2 hh = __floats2half2_rn(a, b);
    float ra = a - __half2float(__low2half(hh));
    float rb = b - __half2float(__high2half(hh));
    __half2 ll = __floats2half2_rn(ra, rb);
    lo = *(uint32_t*)&ll;
    return *(uint32_t*)&hh;
}

// ---------------- fast exp2 (FMA-only) -------------------------------------
__device__ __forceinline__ float fexp2(float t) {
    t = fmaxf(t, -126.0f);
    float z  = t + 12582912.0f;
    int   ei = __float_as_int(z) - 0x4B400000;
    float f  = t - (z - 12582912.0f);
    float p  = 1.33335581e-3f;
    p = fmaf(p, f, 9.61812911e-3f);
    p = fmaf(p, f, 5.55041087e-2f);
    p = fmaf(p, f, 2.40226507e-1f);
    p = fmaf(p, f, 6.93147181e-1f);
    p = fmaf(p, f, 1.0f);
    return __int_as_float(__float_as_int(p) + (ei << 23));
}

// ============================================================================
// fused prep: grid (1024, 5). y=0..2: split q/k/v. y=3: transpose+split 4
// weights. y=4: bit-pack mask.
// ============================================================================
__global__ __launch_bounds__(256)
void prep(const float* __restrict__ q, const float* __restrict__ k,
          const float* __restrict__ v,
          const float* __restrict__ Wq, const float* __restrict__ Wk,
          const float* __restrict__ Wv, const float* __restrict__ Wo,
          const int* __restrict__ mask,
          __half* __restrict__ xh, __half* __restrict__ xl,
          __half* __restrict__ wh, __half* __restrict__ wl,
          uint32_t* __restrict__ bits)
{
    const int y   = blockIdx.y;
    const int bid = blockIdx.x;
    const int tid = threadIdx.x;

    if (y < 3) {
        const int n4 = (int)(MD / 4);
        const float* x = (y == 0) ? q : (y == 1) ? k : v;
        const size_t zo = (size_t)y * n4;
        int i = bid * 256 + tid;
        const int stride = 1024 * 256;
        for (; i < n4; i += stride) {
            float4 vv = ((const float4*)x)[i];
            uint2 H, L;
            H.x = pack_split(vv.x, vv.y, L.x);
            H.y = pack_split(vv.z, vv.w, L.y);
            ((uint2*)xh)[zo + i] = H;
            ((uint2*)xl)[zo + i] = L;
        }
    } else if (y == 3) {
        __shared__ float t[32][33];
        const int tx = tid & 31;
        const int ty = tid >> 5;
#pragma unroll
        for (int it = 0; it < 4; ++it) {
            const int z = it;
            const float* W = (z == 0) ? Wq : (z == 1) ? Wk : (z == 2) ? Wv : Wo;
            const size_t zo = (size_t)z * DD;
            const int n0 = (bid & 31) * 32;
            const int k0 = (bid >> 5) * 32;
#pragma unroll
            for (int i = ty; i < 32; i += 8)
                t[i][tx] = W[(size_t)(k0 + i) * DMODEL + n0 + tx];
            __syncthreads();
#pragma unroll
            for (int i = ty; i < 32; i += 8) {
                float vv = t[tx][i];
                __half h = __float2half_rn(vv);
                __half l = __float2half_rn(vv - __half2float(h));
                size_t o = zo + (size_t)(n0 + i) * DMODEL + k0 + tx;
                wh[o] = h;
                wl[o] = l;
            }
            __syncthreads();
        }
    } else {
        const size_t tot = (size_t)BATCH * S_LEN * S_LEN;
        size_t idx = (size_t)bid * 256 + tid;
        const size_t stride = (size_t)1024 * 256;
        for (; idx < tot; idx += stride) {
            int mv = mask[idx];
            uint32_t bal = __ballot_sync(0xffffffffu, mv != 0);
            if ((tid & 31) == 0) bits[idx >> 5] = bal;
        }
    }
}

// ============================================================================
// HMMA split-fp16 GEMM, BM=128 BN=128, 2 CTAs/SM, cp.async double-buffered,
// 3-pass fp32-accumulate (R9 configuration — at the mma.sync floor).
// MODE 0: fp32 out row-major. MODE 1: fp16 hi/lo out in [B,H,S,DK], z-fused;
//         z==0 (Q) output is pre-scaled by SC = 0.125*log2(e).
// ============================================================================
#define TILE_E 5120            // one 128x32 fp16 tile, padded stride 40
#define GM_SMEM (2 * 4 * TILE_E * 2)   // 81920 bytes

template <int MODE>
__global__ __launch_bounds__(256, 2)
void gemm_mma(const __half* __restrict__ Ab_, const __half* __restrict__ Al_,
              const __half* __restrict__ Bh_, const __half* __restrict__ Bl_,
              const float* __restrict__ b0, const float* __restrict__ b1,
              const float* __restrict__ b2, float* __restrict__ C,
              __half* __restrict__ Ch_, __half* __restrict__ Cl_)
{
    extern __shared__ __half smm[];
    const int tid  = threadIdx.x;
    const int lane = tid & 31;
    const int wid  = tid >> 5;
    const int wm   = wid >> 2;
    const int wn   = wid & 3;
    const int bx   = blockIdx.x;
    const int by   = blockIdx.y;
    const int z    = blockIdx.z;
    const uint32_t sbase = smem_u32(smm);

    const __half* Ah = Ab_ + (size_t)z * MD;
    const __half* Al = Al_ + (size_t)z * MD;
    const __half* Bh = Bh_ + (size_t)z * DD;
    const __half* Bl = Bl_ + (size_t)z * DD;
    const float* bias = (z == 0) ? b0 : (z == 1) ? b1 : b2;
    __half* Ch = Ch_ + (size_t)z * MD;
    __half* Cl = Cl_ + (size_t)z * MD;
    const float oscale = (MODE == 1 && z == 0) ? 0.18033688011112042f : 1.0f;

    const int lr = tid >> 1;
    const int lc = (tid & 1) * 16;
    const __half* pAh = Ah + (size_t)(by * 128 + lr) * DMODEL + lc;
    const __half* pAl = Al + (size_t)(by * 128 + lr) * DMODEL + lc;
    const __half* pBh = Bh + (size_t)(bx * 128 + lr) * DMODEL + lc;
    const __half* pBl = Bl + (size_t)(bx * 128 + lr) * DMODEL + lc;

    auto copy_stage = [&](int kb, int s) {
        const uint32_t d = sbase + (uint32_t)(s * 4 * TILE_E + lr * 40 + lc) * 2;
        const int go = kb * 32;
        cpa16(d,                    pAh + go);
        cpa16(d + 16,               pAh + go + 8);
        cpa16(d + TILE_E * 2,       pAl + go);
        cpa16(d + TILE_E * 2 + 16,  pAl + go + 8);
        cpa16(d + 4 * TILE_E,       pBh + go);
        cpa16(d + 4 * TILE_E + 16,  pBh + go + 8);
        cpa16(d + 6 * TILE_E,       pBl + go);
        cpa16(d + 6 * TILE_E + 16,  pBl + go + 8);
    };

    float acc[4][4][4];
#pragma unroll
    for (int i = 0; i < 4; ++i)
#pragma unroll
        for (int j = 0; j < 4; ++j)
#pragma unroll
            for (int r = 0; r < 4; ++r) acc[i][j][r] = 0.0f;

    copy_stage(0, 0);
    CP_COMMIT();

    const int NKB = DMODEL / 32;
    for (int kb = 0; kb < NKB; ++kb) {
        const int cur = kb & 1;
        if (kb + 1 < NKB) {
            copy_stage(kb + 1, 1 - cur);
            CP_COMMIT();
            CP_WAIT(1);
        } else {
            CP_WAIT(0);
        }
        __syncthreads();

        const uint32_t stA = sbase + (uint32_t)(cur * 4) * TILE_E * 2;
        const uint32_t stB = stA + 2u * TILE_E * 2;
#pragma unroll
        for (int ks = 0; ks < 2; ++ks) {
            uint32_t ah[4][4], al[4][4], bh[4][2], bl[4][2];
            const int ca = ks * 16 + (lane >> 4) * 8;
#pragma unroll
            for (int mi = 0; mi < 4; ++mi) {
                const int ra = wm * 64 + mi * 16 + (lane & 15);
                const uint32_t ad = stA + (uint32_t)(ra * 40 + ca) * 2;
                ldsm_x4(ah[mi], ad);
                ldsm_x4(al[mi], ad + TILE_E * 2);
            }
            const int cb = ks * 16 + ((lane >> 3) & 1) * 8;
#pragma unroll
            for (int nj = 0; nj < 4; ++nj) {
                const int rb = wn * 32 + nj * 8 + (lane & 7);
                const uint32_t bd = stB + (uint32_t)(rb * 40 + cb) * 2;
                ldsm_x2(bh[nj], bd);
                ldsm_x2(bl[nj], bd + TILE_E * 2);
            }
#pragma unroll
            for (int mi = 0; mi < 4; ++mi)
#pragma unroll
                for (int nj = 0; nj < 4; ++nj)
                    mma16816(acc[mi][nj], ah[mi], bh[nj]);
#pragma unroll
            for (int mi = 0; mi < 4; ++mi)
#pragma unroll
                for (int nj = 0; nj < 4; ++nj)
                    mma16816(acc[mi][nj], al[mi], bh[nj]);
#pragma unroll
            for (int mi = 0; mi < 4; ++mi)
#pragma unroll
                for (int nj = 0; nj < 4; ++nj)
                    mma16816(acc[mi][nj], ah[mi], bl[nj]);
        }
        __syncthreads();
    }

#pragma unroll
    for (int mi = 0; mi < 4; ++mi) {
        const int r0 = by * 128 + wm * 64 + mi * 16 + (lane >> 2);
#pragma unroll
        for (int nj = 0; nj < 4; ++nj) {
            const int col = bx * 128 + wn * 32 + nj * 8 + (lane & 3) * 2;
            const float2 bv = *(const float2*)(bias + col);
            float2 v0, v1;
            v0.x = (acc[mi][nj][0] + bv.x) * oscale;
            v0.y = (acc[mi][nj][1] + bv.y) * oscale;
            v1.x = (acc[mi][nj][2] + bv.x) * oscale;
            v1.y = (acc[mi][nj][3] + bv.y) * oscale;
            if (MODE == 1) {
                const int h  = col >> 6;
                const int dk = col & 63;
                const int b0i = r0 >> 11, s0r = r0 & (S_LEN - 1);
                const int r1 = r0 + 8;
                const int b1i = r1 >> 11, s1r = r1 & (S_LEN - 1);
                size_t i0 = (((size_t)b0i * NH + h) * S_LEN + s0r) * HDK + dk;
                size_t i1 = (((size_t)b1i * NH + h) * S_LEN + s1r) * HDK + dk;
                uint32_t l0, l1;
                uint32_t h0 = pack_split(v0.x, v0.y, l0);
                uint32_t h1 = pack_split(v1.x, v1.y, l1);
                *(uint32_t*)(Ch + i0) = h0;
                *(uint32_t*)(Cl + i0) = l0;
                *(uint32_t*)(Ch + i1) = h1;
                *(uint32_t*)(Cl + i1) = l1;
            } else {
                *(float2*)(C + (size_t)r0 * DMODEL + col) = v0;
                *(float2*)(C + (size_t)(r0 + 8) * DMODEL + col) = v1;
            }
        }
    }
}

// ============================================================================
// Flash attention, 2-pass split-fp16 HMMA (S = QhKh + QlKh; O += PhVh + PlVh).
// Kl/Vl never read -> KV stage halves; Q hi/lo persistent in its own region.
// ============================================================================
#define AST 72                         // smem row stride in fp16 (64 + 8 pad)
#define KV_TILE_B (64 * AST * 2)       // 9216 bytes per 64x64 tile
#define STAGE_B   (2 * KV_TILE_B)      // 18432 bytes per stage (Kh, Vh)
#define QOFF_B    (2 * STAGE_B)        // 36864: Q region (128 hi + 128 lo rows)
#define ATT_SMEM  (QOFF_B + 2 * 128 * AST * 2)   // 73728 bytes

__global__ __launch_bounds__(256, 2)
void attn_mma(void)
{
    extern __shared__ __half sma[];
    const int tid  = threadIdx.x;
    const int lane = tid & 31;
    const int w    = tid >> 5;
    const int h    = blockIdx.x;
    const int qt   = blockIdx.y;
    const int b    = blockIdx.z;
    const uint32_t sb = smem_u32(sma);

    const size_t headoff = ((size_t)b * NH + h) * S_LEN * HDK;
    const __half* Qhg = g_Ph + headoff + (size_t)qt * 128 * HDK;
    const __half* Qlg = g_Pl + headoff + (size_t)qt * 128 * HDK;
    const __half* Khg = g_Ph + MD + headoff;
    const __half* Vhg = g_Ph + 2 * MD + headoff;

    auto copy_kv = [&](int kt, int s) {
        const int row = tid >> 2;
        const int c0  = (tid & 3) * 16;
        const size_t g = ((size_t)kt * 64 + row) * HDK + c0;
        const uint32_t d = sb + (uint32_t)(s * STAGE_B)
                         + (uint32_t)(row * AST + c0) * 2;
        cpa16(d,                  Khg + g);
        cpa16(d + 16,             Khg + g + 8);
        cpa16(d + KV_TILE_B,      Vhg + g);
        cpa16(d + KV_TILE_B + 16, Vhg + g + 8);
    };

    copy_kv(0, 0);
    CP_COMMIT();

    {   // Q (128x64 hi + lo) -> persistent Q region (plain stores, once)
        __half* Qs = sma + QOFF_B / 2;
        const int row = tid >> 1;
        const int c0  = (tid & 1) * 32;
#pragma unroll
        for (int i = 0; i < 4; ++i) {
            *(uint4*)(Qs + row * AST + c0 + i * 8) =
                *(const uint4*)(Qhg + (size_t)row * HDK + c0 + i * 8);
            *(uint4*)(Qs + 128 * AST + row * AST + c0 + i * 8) =
                *(const uint4*)(Qlg + (size_t)row * HDK + c0 + i * 8);
        }
    }
    __syncthreads();
    uint32_t qh[4][4], ql[4][4];
#pragma unroll
    for (int kc = 0; kc < 4; ++kc) {
        uint32_t ad = sb + QOFF_B
            + (uint32_t)((w * 16 + (lane & 15)) * AST + kc * 16 + (lane >> 4) * 8) * 2;
        ldsm_x4(qh[kc], ad);
        ldsm_x4(ql[kc], ad + 128 * AST * 2);
    }

    float o[8][4];
#pragma unroll
    for (int i = 0; i < 8; ++i)
#pragma unroll
        for (int j = 0; j < 4; ++j) o[i][j] = 0.0f;
    float l0 = 0.0f, l1 = 0.0f;

    const int qrow0 = qt * 128 + w * 16 + (lane >> 2);
    const uint32_t* mb0 = g_Mb + ((size_t)b * S_LEN + qrow0) * (S_LEN / 32);
    const uint32_t* mb1 = mb0 + 8 * (S_LEN / 32);

    const int NKT = S_LEN / 64;
    for (int kt = 0; kt < NKT; ++kt) {
        const int cur = kt & 1;
        if (kt + 1 < NKT) {
            copy_kv(kt + 1, 1 - cur);
            CP_COMMIT();
            CP_WAIT(1);
        } else {
            CP_WAIT(0);
        }
        __syncthreads();

        const uint2 mu0 = *(const uint2*)(mb0 + 2 * kt);
        const uint2 mu1 = *(const uint2*)(mb1 + 2 * kt);

        const uint32_t st = sb + (uint32_t)(cur * STAGE_B);

        // ---- S = Q K^T (QhKh + QlKh); Q pre-scaled by SC ----
        float s[8][4];
#pragma unroll
        for (int i = 0; i < 8; ++i)
#pragma unroll
            for (int j = 0; j < 4; ++j) s[i][j] = 0.0f;

#pragma unroll
        for (int kc2 = 0; kc2 < 2; ++kc2) {
#pragma unroll
            for (int nj = 0; nj < 8; ++nj) {
                uint32_t bh[4];
                uint32_t ad = st + (uint32_t)((nj * 8 + (lane & 7)) * AST
                                  + kc2 * 32 + (lane >> 3) * 8) * 2;
                ldsm_x4(bh, ad);
                mma16816(s[nj], qh[2 * kc2],     bh);
                mma16816(s[nj], qh[2 * kc2 + 1], bh + 2);
                mma16816(s[nj], ql[2 * kc2],     bh);
                mma16816(s[nj], ql[2 * kc2 + 1], bh + 2);
            }
        }

        // ---- mask + exp2 + local row sums (scores already in log2 units) ----
        float rs0 = 0.0f, rs1 = 0.0f;
        if ((mu0.x & mu0.y & mu1.x & mu1.y) == 0xffffffffu) {
#pragma unroll
            for (int nj = 0; nj < 8; ++nj) {
                s[nj][0] = fexp2(s[nj][0]);
                s[nj][1] = fexp2(s[nj][1]);
                s[nj][2] = fexp2(s[nj][2]);
                s[nj][3] = fexp2(s[nj][3]);
                rs0 += s[nj][0] + s[nj][1];
                rs1 += s[nj][2] + s[nj][3];
            }
        } else {
#pragma unroll
            for (int nj = 0; nj < 8; ++nj) {
                const uint32_t w0 = (nj < 4) ? mu0.x : mu0.y;
                const uint32_t w1 = (nj < 4) ? mu1.x : mu1.y;
                const int bit = (nj & 3) * 8 + (lane & 3) * 2;
                s[nj][0] = ((w0 >> bit) & 1u)       ? s[nj][0] : -1e9f;
                s[nj][1] = ((w0 >> (bit + 1)) & 1u) ? s[nj][1] : -1e9f;
                s[nj][2] = ((w1 >> bit) & 1u)       ? s[nj][2] : -1e9f;
                s[nj][3] = ((w1 >> (bit + 1)) & 1u) ? s[nj][3] : -1e9f;
                s[nj][0] = fexp2(s[nj][0]);
                s[nj][1] = fexp2(s[nj][1]);
                s[nj][2] = fexp2(s[nj][2]);
                s[nj][3] = fexp2(s[nj][3]);
                rs0 += s[nj][0] + s[nj][1];
                rs1 += s[nj][2] + s[nj][3];
            }
        }
        l0 += rs0;
        l1 += rs1;

        // ---- pack ALL of P to fp16 hi/lo ----
        uint32_t ph[16], pl[16];
#pragma unroll
        for (int nj = 0; nj < 8; ++nj) {
            ph[nj * 2]     = pack_split(s[nj][0], s[nj][1], pl[nj * 2]);
            ph[nj * 2 + 1] = pack_split(s[nj][2], s[nj][3], pl[nj * 2 + 1]);
        }

        // ---- O += P V (PhVh + PlVh) ----
#pragma unroll
        for (int kc2 = 0; kc2 < 2; ++kc2) {
            const uint32_t* phA = ph + kc2 * 8;
            const uint32_t* plA = pl + kc2 * 8;
#pragma unroll
            for (int nj2 = 0; nj2 < 8; ++nj2) {
                uint32_t vh[4];
                uint32_t ad = st + KV_TILE_B
                    + (uint32_t)((kc2 * 32 + lane) * AST + nj2 * 8) * 2;
                ldsm_x4t(vh, ad);
                mma16816(o[nj2], phA,     vh);
                mma16816(o[nj2], phA + 4, vh + 2);
                mma16816(o[nj2], plA,     vh);
                mma16816(o[nj2], plA + 4, vh + 2);
            }
        }
        __syncthreads();
    }

    // ---- reduce row sums once, normalize, write ctx hi/lo ----
    l0 += __shfl_xor_sync(0xffffffffu, l0, 1);
    l0 += __shfl_xor_sync(0xffffffffu, l0, 2);
    l1 += __shfl_xor_sync(0xffffffffu, l1, 1);
    l1 += __shfl_xor_sync(0xffffffffu, l1, 2);
    const float inv0 = 1.0f / l0;
    const float inv1 = 1.0f / l1;
    const size_t base0 = ((size_t)b * S_LEN + qrow0) * DMODEL
                         + h * HDK + (lane & 3) * 2;
    const size_t base1 = base0 + (size_t)8 * DMODEL;
#pragma unroll
    for (int nj2 = 0; nj2 < 8; ++nj2) {
        uint32_t lo0, lo1;
        uint32_t hi0 = pack_split(o[nj2][0] * inv0, o[nj2][1] * inv0, lo0);
        uint32_t hi1 = pack_split(o[nj2][2] * inv1, o[nj2][3] * inv1, lo1);
        *(uint32_t*)(g_Ah + base0 + nj2 * 8) = hi0;
        *(uint32_t*)(g_Al + base0 + nj2 * 8) = lo0;
        *(uint32_t*)(g_Ah + base1 + nj2 * 8) = hi1;
        *(uint32_t*)(g_Al + base1 + nj2 * 8) = lo1;
    }
}

// ---------------- launch ----------------------------------------------------
extern "C" void kernel_launch(void* const* d_in, const int* in_sizes, int n_in,
                              void* d_out, int out_size)
{
    (void)in_sizes; (void)n_in; (void)out_size;
    const float* q  = (const float*)d_in[0];
    const float* k  = (const float*)d_in[1];
    const float* v  = (const float*)d_in[2];
    const int*   mk = (const int*)  d_in[3];
    const float* Wq = (const float*)d_in[4];
    const float* bq = (const float*)d_in[5];
    const float* Wk = (const float*)d_in[6];
    const float* bk = (const float*)d_in[7];
    const float* Wv = (const float*)d_in[8];
    const float* bv = (const float*)d_in[9];
    const float* Wo = (const float*)d_in[10];
    const float* bo = (const float*)d_in[11];
    float* out = (float*)d_out;

    __half *pAh, *pAl, *pPh, *pPl, *pWh, *pWl;
    uint32_t* pMb;
    cudaGetSymbolAddress((void**)&pAh, g_Ah);
    cudaGetSymbolAddress((void**)&pAl, g_Al);
    cudaGetSymbolAddress((void**)&pPh, g_Ph);
    cudaGetSymbolAddress((void**)&pPl, g_Pl);
    cudaGetSymbolAddress((void**)&pWh, g_Wh);
    cudaGetSymbolAddress((void**)&pWl, g_Wl);
    cudaGetSymbolAddress((void**)&pMb, g_Mb);

    cudaFuncSetAttribute(gemm_mma<0>, cudaFuncAttributeMaxDynamicSharedMemorySize, GM_SMEM);
    cudaFuncSetAttribute(gemm_mma<1>, cudaFuncAttributeMaxDynamicSharedMemorySize, GM_SMEM);
    cudaFuncSetAttribute(attn_mma,    cudaFuncAttributeMaxDynamicSharedMemorySize, ATT_SMEM);

    // fused prep: activation splits (y=0..2), weight splits (y=3), mask (y=4)
    prep<<<dim3(1024, 5), 256>>>(q, k, v, Wq, Wk, Wv, Wo, mk,
                                 pAh, pAl, pWh, pWl, pMb);
    // fused Q/K/V projections (Q epilogue pre-scales by SC)
    gemm_mma<1><<<dim3(8, 64, 3), 256, GM_SMEM>>>(pAh, pAl, pWh, pWl,
                                                  bq, bk, bv, nullptr, pPh, pPl);
    // attention (2-pass; writes ctx hi/lo into g_Ah/g_Al slot 0)
    attn_mma<<<dim3(NH, S_LEN / 128, BATCH), 256, ATT_SMEM>>>();
    // output projection (weight slot 3)
    gemm_mma<0><<<dim3(8, 64, 1), 256, GM_SMEM>>>(pAh, pAl, pWh + 3 * DD, pWl + 3 * DD,
                                                  bo, bo, bo, out, nullptr, nullptr);
}

// round 15
// speedup vs baseline: 1.4460x; 1.2449x over previous
#include <cuda_runtime.h>
#include <cuda_fp16.h>
#include <cstdint>
#include <cstddef>

#define BATCH  4
#define S_LEN  2048
#define DMODEL 1024
#define NH     16
#define HDK    64
#define MROWS  (BATCH * S_LEN)   // 8192
#define MD     ((size_t)MROWS * DMODEL)
#define DD     ((size_t)DMODEL * DMODEL)

// ---------------- scratch (device globals; no runtime allocation) ----------
__device__ __half g_Ah[3 * MD];   // GEMM A hi (q,k,v inputs; slot 0 reused for ctx)
__device__ __half g_Al[3 * MD];   // GEMM A lo
__device__ __half g_Ph[3 * MD];   // Q,K,V in [B,H,S,DK], hi (Q pre-scaled by SC)
__device__ __half g_Pl[3 * MD];   // lo (attn reads only Q's lo)
__device__ __half g_Wh[4 * DD];   // weight^T hi [N][K]
__device__ uint32_t g_Mb[(size_t)BATCH * S_LEN * (S_LEN / 32)];  // bit mask

// ---------------- PTX helpers (family-portable) -----------------------------
__device__ __forceinline__ uint32_t smem_u32(const void* p) {
    uint32_t a;
    asm("{ .reg .u64 t; cvta.to.shared.u64 t, %1; cvt.u32.u64 %0, t; }"
        : "=r"(a) : "l"(p));
    return a;
}
__device__ __forceinline__ void ldsm_x4(uint32_t* r, uint32_t addr) {
    asm volatile("ldmatrix.sync.aligned.m8n8.x4.shared.b16 {%0,%1,%2,%3}, [%4];"
                 : "=r"(r[0]), "=r"(r[1]), "=r"(r[2]), "=r"(r[3]) : "r"(addr));
}
__device__ __forceinline__ void ldsm_x4t(uint32_t* r, uint32_t addr) {
    asm volatile("ldmatrix.sync.aligned.m8n8.x4.trans.shared.b16 {%0,%1,%2,%3}, [%4];"
                 : "=r"(r[0]), "=r"(r[1]), "=r"(r[2]), "=r"(r[3]) : "r"(addr));
}
__device__ __forceinline__ void ldsm_x2(uint32_t* r, uint32_t addr) {
    asm volatile("ldmatrix.sync.aligned.m8n8.x2.shared.b16 {%0,%1}, [%2];"
                 : "=r"(r[0]), "=r"(r[1]) : "r"(addr));
}
// fp16 operands, fp32 accumulate
__device__ __forceinline__ void mma16816(float* d, const uint32_t* a,
                                         const uint32_t* b) {
    asm volatile(
        "mma.sync.aligned.m16n8k16.row.col.f32.f16.f16.f32 "
        "{%0,%1,%2,%3}, {%4,%5,%6,%7}, {%8,%9}, {%0,%1,%2,%3};"
        : "+f"(d[0]), "+f"(d[1]), "+f"(d[2]), "+f"(d[3])
        : "r"(a[0]), "r"(a[1]), "r"(a[2]), "r"(a[3]), "r"(b[0]), "r"(b[1]));
}
__device__ __forceinline__ void cpa16(uint32_t dst, const void* src) {
    asm volatile("cp.async.cg.shared.global [%0], [%1], 16;"
                 :: "r"(dst), "l"(src) : "memory");
}
#define CP_COMMIT() asm volatile("cp.async.commit_group;" ::: "memory")
#define CP_WAIT(n)  asm volatile("cp.async.wait_group %0;" :: "n"(n) : "memory")

// pack two fp32 into fp16x2 hi, producing residual fp16x2 lo
__device__ __forceinline__ uint32_t pack_split(float a, float b, uint32_t& lo) {
    __half2 hh = __floats2half2_rn(a, b);
    float ra = a - __half2float(__low2half(hh));
    float rb = b - __half2float(__high2half(hh));
    __half2 ll = __floats2half2_rn(ra, rb);
    lo = *(uint32_t*)&ll;
    return *(uint32_t*)&hh;
}

// ---------------- fast exp2 (FMA-only) -------------------------------------
__device__ __forceinline__ float fexp2(float t) {
    t = fmaxf(t, -126.0f);
    float z  = t + 12582912.0f;
    int   ei = __float_as_int(z) - 0x4B400000;
    float f  = t - (z - 12582912.0f);
    float p  = 1.33335581e-3f;
    p = fmaf(p, f, 9.61812911e-3f);
    p = fmaf(p, f, 5.55041087e-2f);
    p = fmaf(p, f, 2.40226507e-1f);
    p = fmaf(p, f, 6.93147181e-1f);
    p = fmaf(p, f, 1.0f);
    return __int_as_float(__float_as_int(p) + (ei << 23));
}

// ============================================================================
// fused prep: grid (1024, 5). y=0..2: split q/k/v. y=3: transpose+split(hi) 4
// weights (lo no longer needed). y=4: bit-pack mask.
// ============================================================================
__global__ __launch_bounds__(256)
void prep(const float* __restrict__ q, const float* __restrict__ k,
          const float* __restrict__ v,
          const float* __restrict__ Wq, const float* __restrict__ Wk,
          const float* __restrict__ Wv, const float* __restrict__ Wo,
          const int* __restrict__ mask,
          __half* __restrict__ xh, __half* __restrict__ xl,
          __half* __restrict__ wh, uint32_t* __restrict__ bits)
{
    const int y   = blockIdx.y;
    const int bid = blockIdx.x;
    const int tid = threadIdx.x;

    if (y < 3) {
        const int n4 = (int)(MD / 4);
        const float* x = (y == 0) ? q : (y == 1) ? k : v;
        const size_t zo = (size_t)y * n4;
        int i = bid * 256 + tid;
        const int stride = 1024 * 256;
        for (; i < n4; i += stride) {
            float4 vv = ((const float4*)x)[i];
            uint2 H, L;
            H.x = pack_split(vv.x, vv.y, L.x);
            H.y = pack_split(vv.z, vv.w, L.y);
            ((uint2*)xh)[zo + i] = H;
            ((uint2*)xl)[zo + i] = L;
        }
    } else if (y == 3) {
        __shared__ float t[32][33];
        const int tx = tid & 31;
        const int ty = tid >> 5;
#pragma unroll
        for (int it = 0; it < 4; ++it) {
            const int z = it;
            const float* W = (z == 0) ? Wq : (z == 1) ? Wk : (z == 2) ? Wv : Wo;
            const size_t zo = (size_t)z * DD;
            const int n0 = (bid & 31) * 32;
            const int k0 = (bid >> 5) * 32;
#pragma unroll
            for (int i = ty; i < 32; i += 8)
                t[i][tx] = W[(size_t)(k0 + i) * DMODEL + n0 + tx];
            __syncthreads();
#pragma unroll
            for (int i = ty; i < 32; i += 8) {
                float vv = t[tx][i];
                wh[zo + (size_t)(n0 + i) * DMODEL + k0 + tx] = __float2half_rn(vv);
            }
            __syncthreads();
        }
    } else {
        const size_t tot = (size_t)BATCH * S_LEN * S_LEN;
        size_t idx = (size_t)bid * 256 + tid;
        const size_t stride = (size_t)1024 * 256;
        for (; idx < tot; idx += stride) {
            int mv = mask[idx];
            uint32_t bal = __ballot_sync(0xffffffffu, mv != 0);
            if ((tid & 31) == 0) bits[idx >> 5] = bal;
        }
    }
}

// ============================================================================
// HMMA split-fp16 GEMM, BM=128 BN=128, 2 CTAs/SM, cp.async double-buffered,
// 2-pass fp32-accumulate (AhBh + AlBh; X·Wl term dropped, calibrated ~8e-5).
// MODE 0: fp32 out row-major. MODE 1: fp16 hi/lo out in [B,H,S,DK], z-fused;
//         z==0 (Q) output is pre-scaled by SC = 0.125*log2(e).
// ============================================================================
#define TILE_E 5120            // one 128x32 fp16 tile, padded stride 40
#define GM_SMEM (2 * 3 * TILE_E * 2)   // 61440 bytes (Ah, Al, Bh per stage)

template <int MODE>
__global__ __launch_bounds__(256, 2)
void gemm_mma(const __half* __restrict__ Ab_, const __half* __restrict__ Al_,
              const __half* __restrict__ Bh_,
              const float* __restrict__ b0, const float* __restrict__ b1,
              const float* __restrict__ b2, float* __restrict__ C,
              __half* __restrict__ Ch_, __half* __restrict__ Cl_)
{
    extern __shared__ __half smm[];
    const int tid  = threadIdx.x;
    const int lane = tid & 31;
    const int wid  = tid >> 5;
    const int wm   = wid >> 2;
    const int wn   = wid & 3;
    const int bx   = blockIdx.x;
    const int by   = blockIdx.y;
    const int z    = blockIdx.z;
    const uint32_t sbase = smem_u32(smm);

    const __half* Ah = Ab_ + (size_t)z * MD;
    const __half* Al = Al_ + (size_t)z * MD;
    const __half* Bh = Bh_ + (size_t)z * DD;
    const float* bias = (z == 0) ? b0 : (z == 1) ? b1 : b2;
    __half* Ch = Ch_ + (size_t)z * MD;
    __half* Cl = Cl_ + (size_t)z * MD;
    const float oscale = (MODE == 1 && z == 0) ? 0.18033688011112042f : 1.0f;

    const int lr = tid >> 1;
    const int lc = (tid & 1) * 16;
    const __half* pAh = Ah + (size_t)(by * 128 + lr) * DMODEL + lc;
    const __half* pAl = Al + (size_t)(by * 128 + lr) * DMODEL + lc;
    const __half* pBh = Bh + (size_t)(bx * 128 + lr) * DMODEL + lc;

    auto copy_stage = [&](int kb, int s) {
        const uint32_t d = sbase + (uint32_t)(s * 3 * TILE_E + lr * 40 + lc) * 2;
        const int go = kb * 32;
        cpa16(d,                    pAh + go);
        cpa16(d + 16,               pAh + go + 8);
        cpa16(d + TILE_E * 2,       pAl + go);
        cpa16(d + TILE_E * 2 + 16,  pAl + go + 8);
        cpa16(d + 4 * TILE_E,       pBh + go);
        cpa16(d + 4 * TILE_E + 16,  pBh + go + 8);
    };

    float acc[4][4][4];
#pragma unroll
    for (int i = 0; i < 4; ++i)
#pragma unroll
        for (int j = 0; j < 4; ++j)
#pragma unroll
            for (int r = 0; r < 4; ++r) acc[i][j][r] = 0.0f;

    copy_stage(0, 0);
    CP_COMMIT();

    const int NKB = DMODEL / 32;
    for (int kb = 0; kb < NKB; ++kb) {
        const int cur = kb & 1;
        if (kb + 1 < NKB) {
            copy_stage(kb + 1, 1 - cur);
            CP_COMMIT();
            CP_WAIT(1);
        } else {
            CP_WAIT(0);
        }
        __syncthreads();

        const uint32_t stA = sbase + (uint32_t)(cur * 3) * TILE_E * 2;
        const uint32_t stB = stA + 2u * TILE_E * 2;
#pragma unroll
        for (int ks = 0; ks < 2; ++ks) {
            uint32_t ah[4][4], al[4][4], bh[4][2];
            const int ca = ks * 16 + (lane >> 4) * 8;
#pragma unroll
            for (int mi = 0; mi < 4; ++mi) {
                const int ra = wm * 64 + mi * 16 + (lane & 15);
                const uint32_t ad = stA + (uint32_t)(ra * 40 + ca) * 2;
                ldsm_x4(ah[mi], ad);
                ldsm_x4(al[mi], ad + TILE_E * 2);
            }
            const int cb = ks * 16 + ((lane >> 3) & 1) * 8;
#pragma unroll
            for (int nj = 0; nj < 4; ++nj) {
                const int rb = wn * 32 + nj * 8 + (lane & 7);
                ldsm_x2(bh[nj], stB + (uint32_t)(rb * 40 + cb) * 2);
            }
#pragma unroll
            for (int mi = 0; mi < 4; ++mi)
#pragma unroll
                for (int nj = 0; nj < 4; ++nj)
                    mma16816(acc[mi][nj], ah[mi], bh[nj]);
#pragma unroll
            for (int mi = 0; mi < 4; ++mi)
#pragma unroll
                for (int nj = 0; nj < 4; ++nj)
                    mma16816(acc[mi][nj], al[mi], bh[nj]);
        }
        __syncthreads();
    }

#pragma unroll
    for (int mi = 0; mi < 4; ++mi) {
        const int r0 = by * 128 + wm * 64 + mi * 16 + (lane >> 2);
#pragma unroll
        for (int nj = 0; nj < 4; ++nj) {
            const int col = bx * 128 + wn * 32 + nj * 8 + (lane & 3) * 2;
            const float2 bv = *(const float2*)(bias + col);
            float2 v0, v1;
            v0.x = (acc[mi][nj][0] + bv.x) * oscale;
            v0.y = (acc[mi][nj][1] + bv.y) * oscale;
            v1.x = (acc[mi][nj][2] + bv.x) * oscale;
            v1.y = (acc[mi][nj][3] + bv.y) * oscale;
            if (MODE == 1) {
                const int h  = col >> 6;
                const int dk = col & 63;
                const int b0i = r0 >> 11, s0r = r0 & (S_LEN - 1);
                const int r1 = r0 + 8;
                const int b1i = r1 >> 11, s1r = r1 & (S_LEN - 1);
                size_t i0 = (((size_t)b0i * NH + h) * S_LEN + s0r) * HDK + dk;
                size_t i1 = (((size_t)b1i * NH + h) * S_LEN + s1r) * HDK + dk;
                uint32_t l0, l1;
                uint32_t h0 = pack_split(v0.x, v0.y, l0);
                uint32_t h1 = pack_split(v1.x, v1.y, l1);
                *(uint32_t*)(Ch + i0) = h0;
                *(uint32_t*)(Cl + i0) = l0;
                *(uint32_t*)(Ch + i1) = h1;
                *(uint32_t*)(Cl + i1) = l1;
            } else {
                *(float2*)(C + (size_t)r0 * DMODEL + col) = v0;
                *(float2*)(C + (size_t)(r0 + 8) * DMODEL + col) = v1;
            }
        }
    }
}

// ============================================================================
// Flash attention, 2-pass split-fp16 HMMA (S = QhKh + QlKh; O += PhVh + PlVh).
// (unchanged from R14)
// ============================================================================
#define AST 72                         // smem row stride in fp16 (64 + 8 pad)
#define KV_TILE_B (64 * AST * 2)       // 9216 bytes per 64x64 tile
#define STAGE_B   (2 * KV_TILE_B)      // 18432 bytes per stage (Kh, Vh)
#define QOFF_B    (2 * STAGE_B)        // 36864: Q region (128 hi + 128 lo rows)
#define ATT_SMEM  (QOFF_B + 2 * 128 * AST * 2)   // 73728 bytes

__global__ __launch_bounds__(256, 2)
void attn_mma(void)
{
    extern __shared__ __half sma[];
    const int tid  = threadIdx.x;
    const int lane = tid & 31;
    const int w    = tid >> 5;
    const int h    = blockIdx.x;
    const int qt   = blockIdx.y;
    const int b    = blockIdx.z;
    const uint32_t sb = smem_u32(sma);

    const size_t headoff = ((size_t)b * NH + h) * S_LEN * HDK;
    const __half* Qhg = g_Ph + headoff + (size_t)qt * 128 * HDK;
    const __half* Qlg = g_Pl + headoff + (size_t)qt * 128 * HDK;
    const __half* Khg = g_Ph + MD + headoff;
    const __half* Vhg = g_Ph + 2 * MD + headoff;

    auto copy_kv = [&](int kt, int s) {
        const int row = tid >> 2;
        const int c0  = (tid & 3) * 16;
        const size_t g = ((size_t)kt * 64 + row) * HDK + c0;
        const uint32_t d = sb + (uint32_t)(s * STAGE_B)
                         + (uint32_t)(row * AST + c0) * 2;
        cpa16(d,                  Khg + g);
        cpa16(d + 16,             Khg + g + 8);
        cpa16(d + KV_TILE_B,      Vhg + g);
        cpa16(d + KV_TILE_B + 16, Vhg + g + 8);
    };

    copy_kv(0, 0);
    CP_COMMIT();

    {   // Q (128x64 hi + lo) -> persistent Q region (plain stores, once)
        __half* Qs = sma + QOFF_B / 2;
        const int row = tid >> 1;
        const int c0  = (tid & 1) * 32;
#pragma unroll
        for (int i = 0; i < 4; ++i) {
            *(uint4*)(Qs + row * AST + c0 + i * 8) =
                *(const uint4*)(Qhg + (size_t)row * HDK + c0 + i * 8);
            *(uint4*)(Qs + 128 * AST + row * AST + c0 + i * 8) =
                *(const uint4*)(Qlg + (size_t)row * HDK + c0 + i * 8);
        }
    }
    __syncthreads();
    uint32_t qh[4][4], ql[4][4];
#pragma unroll
    for (int kc = 0; kc < 4; ++kc) {
        uint32_t ad = sb + QOFF_B
            + (uint32_t)((w * 16 + (lane & 15)) * AST + kc * 16 + (lane >> 4) * 8) * 2;
        ldsm_x4(qh[kc], ad);
        ldsm_x4(ql[kc], ad + 128 * AST * 2);
    }

    float o[8][4];
#pragma unroll
    for (int i = 0; i < 8; ++i)
#pragma unroll
        for (int j = 0; j < 4; ++j) o[i][j] = 0.0f;
    float l0 = 0.0f, l1 = 0.0f;

    const int qrow0 = qt * 128 + w * 16 + (lane >> 2);
    const uint32_t* mb0 = g_Mb + ((size_t)b * S_LEN + qrow0) * (S_LEN / 32);
    const uint32_t* mb1 = mb0 + 8 * (S_LEN / 32);

    const int NKT = S_LEN / 64;
    for (int kt = 0; kt < NKT; ++kt) {
        const int cur = kt & 1;
        if (kt + 1 < NKT) {
            copy_kv(kt + 1, 1 - cur);
            CP_COMMIT();
            CP_WAIT(1);
        } else {
            CP_WAIT(0);
        }
        __syncthreads();

        const uint2 mu0 = *(const uint2*)(mb0 + 2 * kt);
        const uint2 mu1 = *(const uint2*)(mb1 + 2 * kt);

        const uint32_t st = sb + (uint32_t)(cur * STAGE_B);

        // ---- S = Q K^T (QhKh + QlKh); Q pre-scaled by SC ----
        float s[8][4];
#pragma unroll
        for (int i = 0; i < 8; ++i)
#pragma unroll
            for (int j = 0; j < 4; ++j) s[i][j] = 0.0f;

#pragma unroll
        for (int kc2 = 0; kc2 < 2; ++kc2) {
#pragma unroll
            for (int nj = 0; nj < 8; ++nj) {
                uint32_t bh[4];
                uint32_t ad = st + (uint32_t)((nj * 8 + (lane & 7)) * AST
                                  + kc2 * 32 + (lane >> 3) * 8) * 2;
                ldsm_x4(bh, ad);
                mma16816(s[nj], qh[2 * kc2],     bh);
                mma16816(s[nj], qh[2 * kc2 + 1], bh + 2);
                mma16816(s[nj], ql[2 * kc2],     bh);
                mma16816(s[nj], ql[2 * kc2 + 1], bh + 2);
            }
        }

        // ---- mask + exp2 + local row sums ----
        float rs0 = 0.0f, rs1 = 0.0f;
        if ((mu0.x & mu0.y & mu1.x & mu1.y) == 0xffffffffu) {
#pragma unroll
            for (int nj = 0; nj < 8; ++nj) {
                s[nj][0] = fexp2(s[nj][0]);
                s[nj][1] = fexp2(s[nj][1]);
                s[nj][2] = fexp2(s[nj][2]);
                s[nj][3] = fexp2(s[nj][3]);
                rs0 += s[nj][0] + s[nj][1];
                rs1 += s[nj][2] + s[nj][3];
            }
        } else {
#pragma unroll
            for (int nj = 0; nj < 8; ++nj) {
                const uint32_t w0 = (nj < 4) ? mu0.x : mu0.y;
                const uint32_t w1 = (nj < 4) ? mu1.x : mu1.y;
                const int bit = (nj & 3) * 8 + (lane & 3) * 2;
                s[nj][0] = ((w0 >> bit) & 1u)       ? s[nj][0] : -1e9f;
                s[nj][1] = ((w0 >> (bit + 1)) & 1u) ? s[nj][1] : -1e9f;
                s[nj][2] = ((w1 >> bit) & 1u)       ? s[nj][2] : -1e9f;
                s[nj][3] = ((w1 >> (bit + 1)) & 1u) ? s[nj][3] : -1e9f;
                s[nj][0] = fexp2(s[nj][0]);
                s[nj][1] = fexp2(s[nj][1]);
                s[nj][2] = fexp2(s[nj][2]);
                s[nj][3] = fexp2(s[nj][3]);
                rs0 += s[nj][0] + s[nj][1];
                rs1 += s[nj][2] + s[nj][3];
            }
        }
        l0 += rs0;
        l1 += rs1;

        // ---- pack ALL of P to fp16 hi/lo ----
        uint32_t ph[16], pl[16];
#pragma unroll
        for (int nj = 0; nj < 8; ++nj) {
            ph[nj * 2]     = pack_split(s[nj][0], s[nj][1], pl[nj * 2]);
            ph[nj * 2 + 1] = pack_split(s[nj][2], s[nj][3], pl[nj * 2 + 1]);
        }

        // ---- O += P V (PhVh + PlVh) ----
#pragma unroll
        for (int kc2 = 0; kc2 < 2; ++kc2) {
            const uint32_t* phA = ph + kc2 * 8;
            const uint32_t* plA = pl + kc2 * 8;
#pragma unroll
            for (int nj2 = 0; nj2 < 8; ++nj2) {
                uint32_t vh[4];
                uint32_t ad = st + KV_TILE_B
                    + (uint32_t)((kc2 * 32 + lane) * AST + nj2 * 8) * 2;
                ldsm_x4t(vh, ad);
                mma16816(o[nj2], phA,     vh);
                mma16816(o[nj2], phA + 4, vh + 2);
                mma16816(o[nj2], plA,     vh);
                mma16816(o[nj2], plA + 4, vh + 2);
            }
        }
        __syncthreads();
    }

    // ---- reduce row sums once, normalize, write ctx hi/lo ----
    l0 += __shfl_xor_sync(0xffffffffu, l0, 1);
    l0 += __shfl_xor_sync(0xffffffffu, l0, 2);
    l1 += __shfl_xor_sync(0xffffffffu, l1, 1);
    l1 += __shfl_xor_sync(0xffffffffu, l1, 2);
    const float inv0 = 1.0f / l0;
    const float inv1 = 1.0f / l1;
    const size_t base0 = ((size_t)b * S_LEN + qrow0) * DMODEL
                         + h * HDK + (lane & 3) * 2;
    const size_t base1 = base0 + (size_t)8 * DMODEL;
#pragma unroll
    for (int nj2 = 0; nj2 < 8; ++nj2) {
        uint32_t lo0, lo1;
        uint32_t hi0 = pack_split(o[nj2][0] * inv0, o[nj2][1] * inv0, lo0);
        uint32_t hi1 = pack_split(o[nj2][2] * inv1, o[nj2][3] * inv1, lo1);
        *(uint32_t*)(g_Ah + base0 + nj2 * 8) = hi0;
        *(uint32_t*)(g_Al + base0 + nj2 * 8) = lo0;
        *(uint32_t*)(g_Ah + base1 + nj2 * 8) = hi1;
        *(uint32_t*)(g_Al + base1 + nj2 * 8) = lo1;
    }
}

// ---------------- launch ----------------------------------------------------
extern "C" void kernel_launch(void* const* d_in, const int* in_sizes, int n_in,
                              void* d_out, int out_size)
{
    (void)in_sizes; (void)n_in; (void)out_size;
    const float* q  = (const float*)d_in[0];
    const float* k  = (const float*)d_in[1];
    const float* v  = (const float*)d_in[2];
    const int*   mk = (const int*)  d_in[3];
    const float* Wq = (const float*)d_in[4];
    const float* bq = (const float*)d_in[5];
    const float* Wk = (const float*)d_in[6];
    const float* bk = (const float*)d_in[7];
    const float* Wv = (const float*)d_in[8];
    const float* bv = (const float*)d_in[9];
    const float* Wo = (const float*)d_in[10];
    const float* bo = (const float*)d_in[11];
    float* out = (float*)d_out;

    __half *pAh, *pAl, *pPh, *pPl, *pWh;
    uint32_t* pMb;
    cudaGetSymbolAddress((void**)&pAh, g_Ah);
    cudaGetSymbolAddress((void**)&pAl, g_Al);
    cudaGetSymbolAddress((void**)&pPh, g_Ph);
    cudaGetSymbolAddress((void**)&pPl, g_Pl);
    cudaGetSymbolAddress((void**)&pWh, g_Wh);
    cudaGetSymbolAddress((void**)&pMb, g_Mb);

    cudaFuncSetAttribute(gemm_mma<0>, cudaFuncAttributeMaxDynamicSharedMemorySize, GM_SMEM);
    cudaFuncSetAttribute(gemm_mma<1>, cudaFuncAttributeMaxDynamicSharedMemorySize, GM_SMEM);
    cudaFuncSetAttribute(attn_mma,    cudaFuncAttributeMaxDynamicSharedMemorySize, ATT_SMEM);

    // fused prep: activation splits (y=0..2), weight hi (y=3), mask (y=4)
    prep<<<dim3(1024, 5), 256>>>(q, k, v, Wq, Wk, Wv, Wo, mk,
                                 pAh, pAl, pWh, pMb);
    // fused Q/K/V projections (2-pass; Q epilogue pre-scales by SC)
    gemm_mma<1><<<dim3(8, 64, 3), 256, GM_SMEM>>>(pAh, pAl, pWh,
                                                  bq, bk, bv, nullptr, pPh, pPl);
    // attention (2-pass; writes ctx hi/lo into g_Ah/g_Al slot 0)
    attn_mma<<<dim3(NH, S_LEN / 128, BATCH), 256, ATT_SMEM>>>();
    // output projection (2-pass; weight slot 3)
    gemm_mma<0><<<dim3(8, 64, 1), 256, GM_SMEM>>>(pAh, pAl, pWh + 3 * DD,
                                                  bo, bo, bo, out, nullptr, nullptr);
}

// round 16
// speedup vs baseline: 1.5807x; 1.0931x over previous
#include <cuda_runtime.h>
#include <cuda_fp16.h>
#include <cstdint>
#include <cstddef>

#define BATCH  4
#define S_LEN  2048
#define DMODEL 1024
#define NH     16
#define HDK    64
#define MROWS  (BATCH * S_LEN)   // 8192
#define MD     ((size_t)MROWS * DMODEL)
#define DD     ((size_t)DMODEL * DMODEL)

// ---------------- scratch (device globals; no runtime allocation) ----------
__device__ __half g_Ah[3 * MD];   // GEMM A hi (q,k,v inputs; slot 0 reused for ctx)
__device__ __half g_Al[3 * MD];   // GEMM A lo
__device__ __half g_Ph[3 * MD];   // Q,K,V in [B,H,S,DK], hi (Q pre-scaled by SC)
__device__ __half g_Wh[4 * DD];   // weight^T hi [N][K]
__device__ uint32_t g_Mb[(size_t)BATCH * S_LEN * (S_LEN / 32)];  // bit mask

// ---------------- PTX helpers (family-portable) -----------------------------
__device__ __forceinline__ uint32_t smem_u32(const void* p) {
    uint32_t a;
    asm("{ .reg .u64 t; cvta.to.shared.u64 t, %1; cvt.u32.u64 %0, t; }"
        : "=r"(a) : "l"(p));
    return a;
}
__device__ __forceinline__ void ldsm_x4(uint32_t* r, uint32_t addr) {
    asm volatile("ldmatrix.sync.aligned.m8n8.x4.shared.b16 {%0,%1,%2,%3}, [%4];"
                 : "=r"(r[0]), "=r"(r[1]), "=r"(r[2]), "=r"(r[3]) : "r"(addr));
}
__device__ __forceinline__ void ldsm_x4t(uint32_t* r, uint32_t addr) {
    asm volatile("ldmatrix.sync.aligned.m8n8.x4.trans.shared.b16 {%0,%1,%2,%3}, [%4];"
                 : "=r"(r[0]), "=r"(r[1]), "=r"(r[2]), "=r"(r[3]) : "r"(addr));
}
__device__ __forceinline__ void ldsm_x2(uint32_t* r, uint32_t addr) {
    asm volatile("ldmatrix.sync.aligned.m8n8.x2.shared.b16 {%0,%1}, [%2];"
                 : "=r"(r[0]), "=r"(r[1]) : "r"(addr));
}
// fp16 operands, fp32 accumulate
__device__ __forceinline__ void mma16816(float* d, const uint32_t* a,
                                         const uint32_t* b) {
    asm volatile(
        "mma.sync.aligned.m16n8k16.row.col.f32.f16.f16.f32 "
        "{%0,%1,%2,%3}, {%4,%5,%6,%7}, {%8,%9}, {%0,%1,%2,%3};"
        : "+f"(d[0]), "+f"(d[1]), "+f"(d[2]), "+f"(d[3])
        : "r"(a[0]), "r"(a[1]), "r"(a[2]), "r"(a[3]), "r"(b[0]), "r"(b[1]));
}
__device__ __forceinline__ void cpa16(uint32_t dst, const void* src) {
    asm volatile("cp.async.cg.shared.global [%0], [%1], 16;"
                 :: "r"(dst), "l"(src) : "memory");
}
#define CP_COMMIT() asm volatile("cp.async.commit_group;" ::: "memory")
#define CP_WAIT(n)  asm volatile("cp.async.wait_group %0;" :: "n"(n) : "memory")

// pack two fp32 into fp16x2 hi, producing residual fp16x2 lo
__device__ __forceinline__ uint32_t pack_split(float a, float b, uint32_t& lo) {
    __half2 hh = __floats2half2_rn(a, b);
    float ra = a - __half2float(__low2half(hh));
    float rb = b - __half2float(__high2half(hh));
    __half2 ll = __floats2half2_rn(ra, rb);
    lo = *(uint32_t*)&ll;
    return *(uint32_t*)&hh;
}

// ---------------- fast exp2 (FMA-only) -------------------------------------
__device__ __forceinline__ float fexp2(float t) {
    t = fmaxf(t, -126.0f);
    float z  = t + 12582912.0f;
    int   ei = __float_as_int(z) - 0x4B400000;
    float f  = t - (z - 12582912.0f);
    float p  = 1.33335581e-3f;
    p = fmaf(p, f, 9.61812911e-3f);
    p = fmaf(p, f, 5.55041087e-2f);
    p = fmaf(p, f, 2.40226507e-1f);
    p = fmaf(p, f, 6.93147181e-1f);
    p = fmaf(p, f, 1.0f);
    return __int_as_float(__float_as_int(p) + (ei << 23));
}

// ============================================================================
// fused prep: grid (1024, 5). y=0..2: split q/k/v. y=3: transpose 4 weights
// to hi fp16. y=4: bit-pack mask.
// ============================================================================
__global__ __launch_bounds__(256)
void prep(const float* __restrict__ q, const float* __restrict__ k,
          const float* __restrict__ v,
          const float* __restrict__ Wq, const float* __restrict__ Wk,
          const float* __restrict__ Wv, const float* __restrict__ Wo,
          const int* __restrict__ mask,
          __half* __restrict__ xh, __half* __restrict__ xl,
          __half* __restrict__ wh, uint32_t* __restrict__ bits)
{
    const int y   = blockIdx.y;
    const int bid = blockIdx.x;
    const int tid = threadIdx.x;

    if (y < 3) {
        const int n4 = (int)(MD / 4);
        const float* x = (y == 0) ? q : (y == 1) ? k : v;
        const size_t zo = (size_t)y * n4;
        int i = bid * 256 + tid;
        const int stride = 1024 * 256;
        for (; i < n4; i += stride) {
            float4 vv = ((const float4*)x)[i];
            uint2 H, L;
            H.x = pack_split(vv.x, vv.y, L.x);
            H.y = pack_split(vv.z, vv.w, L.y);
            ((uint2*)xh)[zo + i] = H;
            ((uint2*)xl)[zo + i] = L;
        }
    } else if (y == 3) {
        __shared__ float t[32][33];
        const int tx = tid & 31;
        const int ty = tid >> 5;
#pragma unroll
        for (int it = 0; it < 4; ++it) {
            const int z = it;
            const float* W = (z == 0) ? Wq : (z == 1) ? Wk : (z == 2) ? Wv : Wo;
            const size_t zo = (size_t)z * DD;
            const int n0 = (bid & 31) * 32;
            const int k0 = (bid >> 5) * 32;
#pragma unroll
            for (int i = ty; i < 32; i += 8)
                t[i][tx] = W[(size_t)(k0 + i) * DMODEL + n0 + tx];
            __syncthreads();
#pragma unroll
            for (int i = ty; i < 32; i += 8) {
                float vv = t[tx][i];
                wh[zo + (size_t)(n0 + i) * DMODEL + k0 + tx] = __float2half_rn(vv);
            }
            __syncthreads();
        }
    } else {
        const size_t tot = (size_t)BATCH * S_LEN * S_LEN;
        size_t idx = (size_t)bid * 256 + tid;
        const size_t stride = (size_t)1024 * 256;
        for (; idx < tot; idx += stride) {
            int mv = mask[idx];
            uint32_t bal = __ballot_sync(0xffffffffu, mv != 0);
            if ((tid & 31) == 0) bits[idx >> 5] = bal;
        }
    }
}

// ============================================================================
// HMMA split-fp16 GEMM, BM=128 BN=128, 2 CTAs/SM, cp.async double-buffered,
// 2-pass fp32-accumulate (AhBh + AlBh).
// MODE 0: fp32 out row-major. MODE 1: fp16 hi-only out [B,H,S,DK], z-fused;
//         z==0 (Q) output pre-scaled by SC = 0.125*log2(e).
// ============================================================================
#define TILE_E 5120            // one 128x32 fp16 tile, padded stride 40
#define GM_SMEM (2 * 3 * TILE_E * 2)   // 61440 bytes (Ah, Al, Bh per stage)

template <int MODE>
__global__ __launch_bounds__(256, 2)
void gemm_mma(const __half* __restrict__ Ab_, const __half* __restrict__ Al_,
              const __half* __restrict__ Bh_,
              const float* __restrict__ b0, const float* __restrict__ b1,
              const float* __restrict__ b2, float* __restrict__ C,
              __half* __restrict__ Ch_)
{
    extern __shared__ __half smm[];
    const int tid  = threadIdx.x;
    const int lane = tid & 31;
    const int wid  = tid >> 5;
    const int wm   = wid >> 2;
    const int wn   = wid & 3;
    const int bx   = blockIdx.x;
    const int by   = blockIdx.y;
    const int z    = blockIdx.z;
    const uint32_t sbase = smem_u32(smm);

    const __half* Ah = Ab_ + (size_t)z * MD;
    const __half* Al = Al_ + (size_t)z * MD;
    const __half* Bh = Bh_ + (size_t)z * DD;
    const float* bias = (z == 0) ? b0 : (z == 1) ? b1 : b2;
    __half* Ch = Ch_ + (size_t)z * MD;
    const float oscale = (MODE == 1 && z == 0) ? 0.18033688011112042f : 1.0f;

    const int lr = tid >> 1;
    const int lc = (tid & 1) * 16;
    const __half* pAh = Ah + (size_t)(by * 128 + lr) * DMODEL + lc;
    const __half* pAl = Al + (size_t)(by * 128 + lr) * DMODEL + lc;
    const __half* pBh = Bh + (size_t)(bx * 128 + lr) * DMODEL + lc;

    auto copy_stage = [&](int kb, int s) {
        const uint32_t d = sbase + (uint32_t)(s * 3 * TILE_E + lr * 40 + lc) * 2;
        const int go = kb * 32;
        cpa16(d,                    pAh + go);
        cpa16(d + 16,               pAh + go + 8);
        cpa16(d + TILE_E * 2,       pAl + go);
        cpa16(d + TILE_E * 2 + 16,  pAl + go + 8);
        cpa16(d + 4 * TILE_E,       pBh + go);
        cpa16(d + 4 * TILE_E + 16,  pBh + go + 8);
    };

    float acc[4][4][4];
#pragma unroll
    for (int i = 0; i < 4; ++i)
#pragma unroll
        for (int j = 0; j < 4; ++j)
#pragma unroll
            for (int r = 0; r < 4; ++r) acc[i][j][r] = 0.0f;

    copy_stage(0, 0);
    CP_COMMIT();

    const int NKB = DMODEL / 32;
    for (int kb = 0; kb < NKB; ++kb) {
        const int cur = kb & 1;
        if (kb + 1 < NKB) {
            copy_stage(kb + 1, 1 - cur);
            CP_COMMIT();
            CP_WAIT(1);
        } else {
            CP_WAIT(0);
        }
        __syncthreads();

        const uint32_t stA = sbase + (uint32_t)(cur * 3) * TILE_E * 2;
        const uint32_t stB = stA + 2u * TILE_E * 2;
#pragma unroll
        for (int ks = 0; ks < 2; ++ks) {
            uint32_t ah[4][4], al[4][4], bh[4][2];
            const int ca = ks * 16 + (lane >> 4) * 8;
#pragma unroll
            for (int mi = 0; mi < 4; ++mi) {
                const int ra = wm * 64 + mi * 16 + (lane & 15);
                const uint32_t ad = stA + (uint32_t)(ra * 40 + ca) * 2;
                ldsm_x4(ah[mi], ad);
                ldsm_x4(al[mi], ad + TILE_E * 2);
            }
            const int cb = ks * 16 + ((lane >> 3) & 1) * 8;
#pragma unroll
            for (int nj = 0; nj < 4; ++nj) {
                const int rb = wn * 32 + nj * 8 + (lane & 7);
                ldsm_x2(bh[nj], stB + (uint32_t)(rb * 40 + cb) * 2);
            }
#pragma unroll
            for (int mi = 0; mi < 4; ++mi)
#pragma unroll
                for (int nj = 0; nj < 4; ++nj)
                    mma16816(acc[mi][nj], ah[mi], bh[nj]);
#pragma unroll
            for (int mi = 0; mi < 4; ++mi)
#pragma unroll
                for (int nj = 0; nj < 4; ++nj)
                    mma16816(acc[mi][nj], al[mi], bh[nj]);
        }
        __syncthreads();
    }

#pragma unroll
    for (int mi = 0; mi < 4; ++mi) {
        const int r0 = by * 128 + wm * 64 + mi * 16 + (lane >> 2);
#pragma unroll
        for (int nj = 0; nj < 4; ++nj) {
            const int col = bx * 128 + wn * 32 + nj * 8 + (lane & 3) * 2;
            const float2 bv = *(const float2*)(bias + col);
            float2 v0, v1;
            v0.x = (acc[mi][nj][0] + bv.x) * oscale;
            v0.y = (acc[mi][nj][1] + bv.y) * oscale;
            v1.x = (acc[mi][nj][2] + bv.x) * oscale;
            v1.y = (acc[mi][nj][3] + bv.y) * oscale;
            if (MODE == 1) {
                const int h  = col >> 6;
                const int dk = col & 63;
                const int b0i = r0 >> 11, s0r = r0 & (S_LEN - 1);
                const int r1 = r0 + 8;
                const int b1i = r1 >> 11, s1r = r1 & (S_LEN - 1);
                size_t i0 = (((size_t)b0i * NH + h) * S_LEN + s0r) * HDK + dk;
                size_t i1 = (((size_t)b1i * NH + h) * S_LEN + s1r) * HDK + dk;
                __half2 h0 = __floats2half2_rn(v0.x, v0.y);
                __half2 h1 = __floats2half2_rn(v1.x, v1.y);
                *(__half2*)(Ch + i0) = h0;
                *(__half2*)(Ch + i1) = h1;
            } else {
                *(float2*)(C + (size_t)r0 * DMODEL + col) = v0;
                *(float2*)(C + (size_t)(r0 + 8) * DMODEL + col) = v1;
            }
        }
    }
}

// ============================================================================
// Flash attention: S = QhKh (1-pass); O += PhVh + PlVh (2-pass).
// Q hi-only persistent region; K/V hi double-buffered.
// ============================================================================
#define AST 72                         // smem row stride in fp16 (64 + 8 pad)
#define KV_TILE_B (64 * AST * 2)       // 9216 bytes per 64x64 tile
#define STAGE_B   (2 * KV_TILE_B)      // 18432 bytes per stage (Kh, Vh)
#define QOFF_B    (2 * STAGE_B)        // 36864: Q region (128 hi rows)
#define ATT_SMEM  (QOFF_B + 128 * AST * 2)   // 55296 bytes

__global__ __launch_bounds__(256, 2)
void attn_mma(void)
{
    extern __shared__ __half sma[];
    const int tid  = threadIdx.x;
    const int lane = tid & 31;
    const int w    = tid >> 5;
    const int h    = blockIdx.x;
    const int qt   = blockIdx.y;
    const int b    = blockIdx.z;
    const uint32_t sb = smem_u32(sma);

    const size_t headoff = ((size_t)b * NH + h) * S_LEN * HDK;
    const __half* Qhg = g_Ph + headoff + (size_t)qt * 128 * HDK;
    const __half* Khg = g_Ph + MD + headoff;
    const __half* Vhg = g_Ph + 2 * MD + headoff;

    auto copy_kv = [&](int kt, int s) {
        const int row = tid >> 2;
        const int c0  = (tid & 3) * 16;
        const size_t g = ((size_t)kt * 64 + row) * HDK + c0;
        const uint32_t d = sb + (uint32_t)(s * STAGE_B)
                         + (uint32_t)(row * AST + c0) * 2;
        cpa16(d,                  Khg + g);
        cpa16(d + 16,             Khg + g + 8);
        cpa16(d + KV_TILE_B,      Vhg + g);
        cpa16(d + KV_TILE_B + 16, Vhg + g + 8);
    };

    copy_kv(0, 0);
    CP_COMMIT();

    {   // Q (128x64 hi) -> persistent Q region (plain stores, once)
        __half* Qs = sma + QOFF_B / 2;
        const int row = tid >> 1;
        const int c0  = (tid & 1) * 32;
#pragma unroll
        for (int i = 0; i < 4; ++i) {
            *(uint4*)(Qs + row * AST + c0 + i * 8) =
                *(const uint4*)(Qhg + (size_t)row * HDK + c0 + i * 8);
        }
    }
    __syncthreads();
    uint32_t qh[4][4];
#pragma unroll
    for (int kc = 0; kc < 4; ++kc) {
        uint32_t ad = sb + QOFF_B
            + (uint32_t)((w * 16 + (lane & 15)) * AST + kc * 16 + (lane >> 4) * 8) * 2;
        ldsm_x4(qh[kc], ad);
    }

    float o[8][4];
#pragma unroll
    for (int i = 0; i < 8; ++i)
#pragma unroll
        for (int j = 0; j < 4; ++j) o[i][j] = 0.0f;
    float l0 = 0.0f, l1 = 0.0f;

    const int qrow0 = qt * 128 + w * 16 + (lane >> 2);
    const uint32_t* mb0 = g_Mb + ((size_t)b * S_LEN + qrow0) * (S_LEN / 32);
    const uint32_t* mb1 = mb0 + 8 * (S_LEN / 32);

    const int NKT = S_LEN / 64;
    for (int kt = 0; kt < NKT; ++kt) {
        const int cur = kt & 1;
        if (kt + 1 < NKT) {
            copy_kv(kt + 1, 1 - cur);
            CP_COMMIT();
            CP_WAIT(1);
        } else {
            CP_WAIT(0);
        }
        __syncthreads();

        const uint2 mu0 = *(const uint2*)(mb0 + 2 * kt);
        const uint2 mu1 = *(const uint2*)(mb1 + 2 * kt);

        const uint32_t st = sb + (uint32_t)(cur * STAGE_B);

        // ---- S = Qh Kh^T (Q pre-scaled by SC) ----
        float s[8][4];
#pragma unroll
        for (int i = 0; i < 8; ++i)
#pragma unroll
            for (int j = 0; j < 4; ++j) s[i][j] = 0.0f;

#pragma unroll
        for (int kc2 = 0; kc2 < 2; ++kc2) {
#pragma unroll
            for (int nj = 0; nj < 8; ++nj) {
                uint32_t bh[4];
                uint32_t ad = st + (uint32_t)((nj * 8 + (lane & 7)) * AST
                                  + kc2 * 32 + (lane >> 3) * 8) * 2;
                ldsm_x4(bh, ad);
                mma16816(s[nj], qh[2 * kc2],     bh);
                mma16816(s[nj], qh[2 * kc2 + 1], bh + 2);
            }
        }

        // ---- mask + exp2 + local row sums ----
        float rs0 = 0.0f, rs1 = 0.0f;
        if ((mu0.x & mu0.y & mu1.x & mu1.y) == 0xffffffffu) {
#pragma unroll
            for (int nj = 0; nj < 8; ++nj) {
                s[nj][0] = fexp2(s[nj][0]);
                s[nj][1] = fexp2(s[nj][1]);
                s[nj][2] = fexp2(s[nj][2]);
                s[nj][3] = fexp2(s[nj][3]);
                rs0 += s[nj][0] + s[nj][1];
                rs1 += s[nj][2] + s[nj][3];
            }
        } else {
#pragma unroll
            for (int nj = 0; nj < 8; ++nj) {
                const uint32_t w0 = (nj < 4) ? mu0.x : mu0.y;
                const uint32_t w1 = (nj < 4) ? mu1.x : mu1.y;
                const int bit = (nj & 3) * 8 + (lane & 3) * 2;
                s[nj][0] = ((w0 >> bit) & 1u)       ? s[nj][0] : -1e9f;
                s[nj][1] = ((w0 >> (bit + 1)) & 1u) ? s[nj][1] : -1e9f;
                s[nj][2] = ((w1 >> bit) & 1u)       ? s[nj][2] : -1e9f;
                s[nj][3] = ((w1 >> (bit + 1)) & 1u) ? s[nj][3] : -1e9f;
                s[nj][0] = fexp2(s[nj][0]);
                s[nj][1] = fexp2(s[nj][1]);
                s[nj][2] = fexp2(s[nj][2]);
                s[nj][3] = fexp2(s[nj][3]);
                rs0 += s[nj][0] + s[nj][1];
                rs1 += s[nj][2] + s[nj][3];
            }
        }
        l0 += rs0;
        l1 += rs1;

        // ---- pack ALL of P to fp16 hi/lo ----
        uint32_t ph[16], pl[16];
#pragma unroll
        for (int nj = 0; nj < 8; ++nj) {
            ph[nj * 2]     = pack_split(s[nj][0], s[nj][1], pl[nj * 2]);
            ph[nj * 2 + 1] = pack_split(s[nj][2], s[nj][3], pl[nj * 2 + 1]);
        }

        // ---- O += P V (PhVh + PlVh) ----
#pragma unroll
        for (int kc2 = 0; kc2 < 2; ++kc2) {
            const uint32_t* phA = ph + kc2 * 8;
            const uint32_t* plA = pl + kc2 * 8;
#pragma unroll
            for (int nj2 = 0; nj2 < 8; ++nj2) {
                uint32_t vh[4];
                uint32_t ad = st + KV_TILE_B
                    + (uint32_t)((kc2 * 32 + lane) * AST + nj2 * 8) * 2;
                ldsm_x4t(vh, ad);
                mma16816(o[nj2], phA,     vh);
                mma16816(o[nj2], phA + 4, vh + 2);
                mma16816(o[nj2], plA,     vh);
                mma16816(o[nj2], plA + 4, vh + 2);
            }
        }
        __syncthreads();
    }

    // ---- reduce row sums once, normalize, write ctx hi/lo ----
    l0 += __shfl_xor_sync(0xffffffffu, l0, 1);
    l0 += __shfl_xor_sync(0xffffffffu, l0, 2);
    l1 += __shfl_xor_sync(0xffffffffu, l1, 1);
    l1 += __shfl_xor_sync(0xffffffffu, l1, 2);
    const float inv0 = 1.0f / l0;
    const float inv1 = 1.0f / l1;
    const size_t base0 = ((size_t)b * S_LEN + qrow0) * DMODEL
                         + h * HDK + (lane & 3) * 2;
    const size_t base1 = base0 + (size_t)8 * DMODEL;
#pragma unroll
    for (int nj2 = 0; nj2 < 8; ++nj2) {
        uint32_t lo0, lo1;
        uint32_t hi0 = pack_split(o[nj2][0] * inv0, o[nj2][1] * inv0, lo0);
        uint32_t hi1 = pack_split(o[nj2][2] * inv1, o[nj2][3] * inv1, lo1);
        *(uint32_t*)(g_Ah + base0 + nj2 * 8) = hi0;
        *(uint32_t*)(g_Al + base0 + nj2 * 8) = lo0;
        *(uint32_t*)(g_Ah + base1 + nj2 * 8) = hi1;
        *(uint32_t*)(g_Al + base1 + nj2 * 8) = lo1;
    }
}

// ---------------- launch ----------------------------------------------------
extern "C" void kernel_launch(void* const* d_in, const int* in_sizes, int n_in,
                              void* d_out, int out_size)
{
    (void)in_sizes; (void)n_in; (void)out_size;
    const float* q  = (const float*)d_in[0];
    const float* k  = (const float*)d_in[1];
    const float* v  = (const float*)d_in[2];
    const int*   mk = (const int*)  d_in[3];
    const float* Wq = (const float*)d_in[4];
    const float* bq = (const float*)d_in[5];
    const float* Wk = (const float*)d_in[6];
    const float* bk = (const float*)d_in[7];
    const float* Wv = (const float*)d_in[8];
    const float* bv = (const float*)d_in[9];
    const float* Wo = (const float*)d_in[10];
    const float* bo = (const float*)d_in[11];
    float* out = (float*)d_out;

    __half *pAh, *pAl, *pPh, *pWh;
    uint32_t* pMb;
    cudaGetSymbolAddress((void**)&pAh, g_Ah);
    cudaGetSymbolAddress((void**)&pAl, g_Al);
    cudaGetSymbolAddress((void**)&pPh, g_Ph);
    cudaGetSymbolAddress((void**)&pWh, g_Wh);
    cudaGetSymbolAddress((void**)&pMb, g_Mb);

    cudaFuncSetAttribute(gemm_mma<0>, cudaFuncAttributeMaxDynamicSharedMemorySize, GM_SMEM);
    cudaFuncSetAttribute(gemm_mma<1>, cudaFuncAttributeMaxDynamicSharedMemorySize, GM_SMEM);
    cudaFuncSetAttribute(attn_mma,    cudaFuncAttributeMaxDynamicSharedMemorySize, ATT_SMEM);

    // fused prep: activation splits (y=0..2), weight hi (y=3), mask (y=4)
    prep<<<dim3(1024, 5), 256>>>(q, k, v, Wq, Wk, Wv, Wo, mk,
                                 pAh, pAl, pWh, pMb);
    // fused Q/K/V projections (2-pass; hi-only output; Q pre-scaled by SC)
    gemm_mma<1><<<dim3(8, 64, 3), 256, GM_SMEM>>>(pAh, pAl, pWh,
                                                  bq, bk, bv, nullptr, pPh);
    // attention (S 1-pass, PV 2-pass; writes ctx hi/lo into g_Ah/g_Al slot 0)
    attn_mma<<<dim3(NH, S_LEN / 128, BATCH), 256, ATT_SMEM>>>();
    // output projection (2-pass; weight slot 3)
    gemm_mma<0><<<dim3(8, 64, 1), 256, GM_SMEM>>>(pAh, pAl, pWh + 3 * DD,
                                                  bo, bo, bo, out, nullptr);
}

// round 17
// speedup vs baseline: 1.9866x; 1.2568x over previous
#include <cuda_runtime.h>
#include <cuda_fp16.h>
#include <cstdint>
#include <cstddef>

#define BATCH  4
#define S_LEN  2048
#define DMODEL 1024
#define NH     16
#define HDK    64
#define MROWS  (BATCH * S_LEN)   // 8192
#define MD     ((size_t)MROWS * DMODEL)
#define DD     ((size_t)DMODEL * DMODEL)

// ---------------- scratch (device globals; no runtime allocation) ----------
__device__ __half g_Ah[3 * MD];   // GEMM A (q,k,v fp16 inputs; slot 0 reused for ctx)
__device__ __half g_Ph[3 * MD];   // Q,K,V in [B,H,S,DK] (Q pre-scaled by SC)
__device__ __half g_Wh[4 * DD];   // weight^T fp16 [N][K]
__device__ uint32_t g_Mb[(size_t)BATCH * S_LEN * (S_LEN / 32)];  // bit mask

// ---------------- PTX helpers (family-portable) -----------------------------
__device__ __forceinline__ uint32_t smem_u32(const void* p) {
    uint32_t a;
    asm("{ .reg .u64 t; cvta.to.shared.u64 t, %1; cvt.u32.u64 %0, t; }"
        : "=r"(a) : "l"(p));
    return a;
}
__device__ __forceinline__ void ldsm_x4(uint32_t* r, uint32_t addr) {
    asm volatile("ldmatrix.sync.aligned.m8n8.x4.shared.b16 {%0,%1,%2,%3}, [%4];"
                 : "=r"(r[0]), "=r"(r[1]), "=r"(r[2]), "=r"(r[3]) : "r"(addr));
}
__device__ __forceinline__ void ldsm_x4t(uint32_t* r, uint32_t addr) {
    asm volatile("ldmatrix.sync.aligned.m8n8.x4.trans.shared.b16 {%0,%1,%2,%3}, [%4];"
                 : "=r"(r[0]), "=r"(r[1]), "=r"(r[2]), "=r"(r[3]) : "r"(addr));
}
__device__ __forceinline__ void ldsm_x2(uint32_t* r, uint32_t addr) {
    asm volatile("ldmatrix.sync.aligned.m8n8.x2.shared.b16 {%0,%1}, [%2];"
                 : "=r"(r[0]), "=r"(r[1]) : "r"(addr));
}
// fp16 operands, fp32 accumulate
__device__ __forceinline__ void mma16816(float* d, const uint32_t* a,
                                         const uint32_t* b) {
    asm volatile(
        "mma.sync.aligned.m16n8k16.row.col.f32.f16.f16.f32 "
        "{%0,%1,%2,%3}, {%4,%5,%6,%7}, {%8,%9}, {%0,%1,%2,%3};"
        : "+f"(d[0]), "+f"(d[1]), "+f"(d[2]), "+f"(d[3])
        : "r"(a[0]), "r"(a[1]), "r"(a[2]), "r"(a[3]), "r"(b[0]), "r"(b[1]));
}
__device__ __forceinline__ void cpa16(uint32_t dst, const void* src) {
    asm volatile("cp.async.cg.shared.global [%0], [%1], 16;"
                 :: "r"(dst), "l"(src) : "memory");
}
#define CP_COMMIT() asm volatile("cp.async.commit_group;" ::: "memory")
#define CP_WAIT(n)  asm volatile("cp.async.wait_group %0;" :: "n"(n) : "memory")

// pack two fp32 into fp16x2 hi, producing residual fp16x2 lo
__device__ __forceinline__ uint32_t pack_split(float a, float b, uint32_t& lo) {
    __half2 hh = __floats2half2_rn(a, b);
    float ra = a - __half2float(__low2half(hh));
    float rb = b - __half2float(__high2half(hh));
    __half2 ll = __floats2half2_rn(ra, rb);
    lo = *(uint32_t*)&ll;
    return *(uint32_t*)&hh;
}

// ---------------- fast exp2 (FMA-only) -------------------------------------
__device__ __forceinline__ float fexp2(float t) {
    t = fmaxf(t, -126.0f);
    float z  = t + 12582912.0f;
    int   ei = __float_as_int(z) - 0x4B400000;
    float f  = t - (z - 12582912.0f);
    float p  = 1.33335581e-3f;
    p = fmaf(p, f, 9.61812911e-3f);
    p = fmaf(p, f, 5.55041087e-2f);
    p = fmaf(p, f, 2.40226507e-1f);
    p = fmaf(p, f, 6.93147181e-1f);
    p = fmaf(p, f, 1.0f);
    return __int_as_float(__float_as_int(p) + (ei << 23));
}

// ============================================================================
// fused prep: grid (1024, 5). y=0..2: convert q/k/v to fp16. y=3: transpose
// 4 weights to fp16. y=4: bit-pack mask.
// ============================================================================
__global__ __launch_bounds__(256)
void prep(const float* __restrict__ q, const float* __restrict__ k,
          const float* __restrict__ v,
          const float* __restrict__ Wq, const float* __restrict__ Wk,
          const float* __restrict__ Wv, const float* __restrict__ Wo,
          const int* __restrict__ mask,
          __half* __restrict__ xh, __half* __restrict__ wh,
          uint32_t* __restrict__ bits)
{
    const int y   = blockIdx.y;
    const int bid = blockIdx.x;
    const int tid = threadIdx.x;

    if (y < 3) {
        const int n4 = (int)(MD / 4);
        const float* x = (y == 0) ? q : (y == 1) ? k : v;
        const size_t zo = (size_t)y * n4;
        int i = bid * 256 + tid;
        const int stride = 1024 * 256;
        for (; i < n4; i += stride) {
            float4 vv = ((const float4*)x)[i];
            __half2 a = __floats2half2_rn(vv.x, vv.y);
            __half2 b = __floats2half2_rn(vv.z, vv.w);
            uint2 H;
            H.x = *(uint32_t*)&a;
            H.y = *(uint32_t*)&b;
            ((uint2*)xh)[zo + i] = H;
        }
    } else if (y == 3) {
        __shared__ float t[32][33];
        const int tx = tid & 31;
        const int ty = tid >> 5;
#pragma unroll
        for (int it = 0; it < 4; ++it) {
            const int z = it;
            const float* W = (z == 0) ? Wq : (z == 1) ? Wk : (z == 2) ? Wv : Wo;
            const size_t zo = (size_t)z * DD;
            const int n0 = (bid & 31) * 32;
            const int k0 = (bid >> 5) * 32;
#pragma unroll
            for (int i = ty; i < 32; i += 8)
                t[i][tx] = W[(size_t)(k0 + i) * DMODEL + n0 + tx];
            __syncthreads();
#pragma unroll
            for (int i = ty; i < 32; i += 8) {
                float vv = t[tx][i];
                wh[zo + (size_t)(n0 + i) * DMODEL + k0 + tx] = __float2half_rn(vv);
            }
            __syncthreads();
        }
    } else {
        const size_t tot = (size_t)BATCH * S_LEN * S_LEN;
        size_t idx = (size_t)bid * 256 + tid;
        const size_t stride = (size_t)1024 * 256;
        for (; idx < tot; idx += stride) {
            int mv = mask[idx];
            uint32_t bal = __ballot_sync(0xffffffffu, mv != 0);
            if ((tid & 31) == 0) bits[idx >> 5] = bal;
        }
    }
}

// ============================================================================
// HMMA fp16 GEMM (1-pass AhBh), BM=128 BN=128, 2 CTAs/SM, cp.async
// double-buffered. MODE 0: fp32 out row-major. MODE 1: fp16 out [B,H,S,DK],
// z-fused; z==0 (Q) output pre-scaled by SC = 0.125*log2(e).
// ============================================================================
#define TILE_E 5120            // one 128x32 fp16 tile, padded stride 40
#define STGB   (2 * TILE_E * 2)       // stage bytes = 20480 (Ah, Bh)
#define GM_SMEM (2 * STGB)            // 40960 bytes

template <int MODE>
__global__ __launch_bounds__(256, 2)
void gemm_mma(const __half* __restrict__ Ab_, const __half* __restrict__ Bh_,
              const float* __restrict__ b0, const float* __restrict__ b1,
              const float* __restrict__ b2, float* __restrict__ C,
              __half* __restrict__ Ch_)
{
    extern __shared__ __half smm[];
    const int tid  = threadIdx.x;
    const int lane = tid & 31;
    const int wid  = tid >> 5;
    const int wm   = wid >> 2;
    const int wn   = wid & 3;
    const int bx   = blockIdx.x;
    const int by   = blockIdx.y;
    const int z    = blockIdx.z;
    const uint32_t sbase = smem_u32(smm);

    const __half* Ah = Ab_ + (size_t)z * MD;
    const __half* Bh = Bh_ + (size_t)z * DD;
    const float* bias = (z == 0) ? b0 : (z == 1) ? b1 : b2;
    __half* Ch = Ch_ + (size_t)z * MD;
    const float oscale = (MODE == 1 && z == 0) ? 0.18033688011112042f : 1.0f;

    const int lr = tid >> 1;
    const int lc = (tid & 1) * 16;
    const __half* pAh = Ah + (size_t)(by * 128 + lr) * DMODEL + lc;
    const __half* pBh = Bh + (size_t)(bx * 128 + lr) * DMODEL + lc;

    auto copy_stage = [&](int kb, int s) {
        const uint32_t d = sbase + (uint32_t)s * STGB + (uint32_t)(lr * 40 + lc) * 2;
        const int go = kb * 32;
        cpa16(d,                    pAh + go);
        cpa16(d + 16,               pAh + go + 8);
        cpa16(d + 2 * TILE_E,       pBh + go);
        cpa16(d + 2 * TILE_E + 16,  pBh + go + 8);
    };

    float acc[4][4][4];
#pragma unroll
    for (int i = 0; i < 4; ++i)
#pragma unroll
        for (int j = 0; j < 4; ++j)
#pragma unroll
            for (int r = 0; r < 4; ++r) acc[i][j][r] = 0.0f;

    copy_stage(0, 0);
    CP_COMMIT();

    const int NKB = DMODEL / 32;
    for (int kb = 0; kb < NKB; ++kb) {
        const int cur = kb & 1;
        if (kb + 1 < NKB) {
            copy_stage(kb + 1, 1 - cur);
            CP_COMMIT();
            CP_WAIT(1);
        } else {
            CP_WAIT(0);
        }
        __syncthreads();

        const uint32_t stA = sbase + (uint32_t)cur * STGB;
        const uint32_t stB = stA + 2u * TILE_E;
#pragma unroll
        for (int ks = 0; ks < 2; ++ks) {
            uint32_t ah[4][4], bh[4][2];
            const int ca = ks * 16 + (lane >> 4) * 8;
#pragma unroll
            for (int mi = 0; mi < 4; ++mi) {
                const int ra = wm * 64 + mi * 16 + (lane & 15);
                ldsm_x4(ah[mi], stA + (uint32_t)(ra * 40 + ca) * 2);
            }
            const int cb = ks * 16 + ((lane >> 3) & 1) * 8;
#pragma unroll
            for (int nj = 0; nj < 4; ++nj) {
                const int rb = wn * 32 + nj * 8 + (lane & 7);
                ldsm_x2(bh[nj], stB + (uint32_t)(rb * 40 + cb) * 2);
            }
#pragma unroll
            for (int mi = 0; mi < 4; ++mi)
#pragma unroll
                for (int nj = 0; nj < 4; ++nj)
                    mma16816(acc[mi][nj], ah[mi], bh[nj]);
        }
        __syncthreads();
    }

#pragma unroll
    for (int mi = 0; mi < 4; ++mi) {
        const int r0 = by * 128 + wm * 64 + mi * 16 + (lane >> 2);
#pragma unroll
        for (int nj = 0; nj < 4; ++nj) {
            const int col = bx * 128 + wn * 32 + nj * 8 + (lane & 3) * 2;
            const float2 bv = *(const float2*)(bias + col);
            float2 v0, v1;
            v0.x = (acc[mi][nj][0] + bv.x) * oscale;
            v0.y = (acc[mi][nj][1] + bv.y) * oscale;
            v1.x = (acc[mi][nj][2] + bv.x) * oscale;
            v1.y = (acc[mi][nj][3] + bv.y) * oscale;
            if (MODE == 1) {
                const int h  = col >> 6;
                const int dk = col & 63;
                const int b0i = r0 >> 11, s0r = r0 & (S_LEN - 1);
                const int r1 = r0 + 8;
                const int b1i = r1 >> 11, s1r = r1 & (S_LEN - 1);
                size_t i0 = (((size_t)b0i * NH + h) * S_LEN + s0r) * HDK + dk;
                size_t i1 = (((size_t)b1i * NH + h) * S_LEN + s1r) * HDK + dk;
                __half2 h0 = __floats2half2_rn(v0.x, v0.y);
                __half2 h1 = __floats2half2_rn(v1.x, v1.y);
                *(__half2*)(Ch + i0) = h0;
                *(__half2*)(Ch + i1) = h1;
            } else {
                *(float2*)(C + (size_t)r0 * DMODEL + col) = v0;
                *(float2*)(C + (size_t)(r0 + 8) * DMODEL + col) = v1;
            }
        }
    }
}

// ============================================================================
// Flash attention: S = QhKh (1-pass); O += PhVh + PlVh (2-pass).
// Q persistent region; K/V double-buffered. ctx written fp16 into g_Ah slot 0.
// ============================================================================
#define AST 72                         // smem row stride in fp16 (64 + 8 pad)
#define KV_TILE_B (64 * AST * 2)       // 9216 bytes per 64x64 tile
#define STAGE_B   (2 * KV_TILE_B)      // 18432 bytes per stage (Kh, Vh)
#define QOFF_B    (2 * STAGE_B)        // 36864: Q region (128 rows)
#define ATT_SMEM  (QOFF_B + 128 * AST * 2)   // 55296 bytes

__global__ __launch_bounds__(256, 2)
void attn_mma(void)
{
    extern __shared__ __half sma[];
    const int tid  = threadIdx.x;
    const int lane = tid & 31;
    const int w    = tid >> 5;
    const int h    = blockIdx.x;
    const int qt   = blockIdx.y;
    const int b    = blockIdx.z;
    const uint32_t sb = smem_u32(sma);

    const size_t headoff = ((size_t)b * NH + h) * S_LEN * HDK;
    const __half* Qhg = g_Ph + headoff + (size_t)qt * 128 * HDK;
    const __half* Khg = g_Ph + MD + headoff;
    const __half* Vhg = g_Ph + 2 * MD + headoff;

    auto copy_kv = [&](int kt, int s) {
        const int row = tid >> 2;
        const int c0  = (tid & 3) * 16;
        const size_t g = ((size_t)kt * 64 + row) * HDK + c0;
        const uint32_t d = sb + (uint32_t)(s * STAGE_B)
                         + (uint32_t)(row * AST + c0) * 2;
        cpa16(d,                  Khg + g);
        cpa16(d + 16,             Khg + g + 8);
        cpa16(d + KV_TILE_B,      Vhg + g);
        cpa16(d + KV_TILE_B + 16, Vhg + g + 8);
    };

    copy_kv(0, 0);
    CP_COMMIT();

    {   // Q (128x64) -> persistent Q region (plain stores, once)
        __half* Qs = sma + QOFF_B / 2;
        const int row = tid >> 1;
        const int c0  = (tid & 1) * 32;
#pragma unroll
        for (int i = 0; i < 4; ++i) {
            *(uint4*)(Qs + row * AST + c0 + i * 8) =
                *(const uint4*)(Qhg + (size_t)row * HDK + c0 + i * 8);
        }
    }
    __syncthreads();
    uint32_t qh[4][4];
#pragma unroll
    for (int kc = 0; kc < 4; ++kc) {
        uint32_t ad = sb + QOFF_B
            + (uint32_t)((w * 16 + (lane & 15)) * AST + kc * 16 + (lane >> 4) * 8) * 2;
        ldsm_x4(qh[kc], ad);
    }

    float o[8][4];
#pragma unroll
    for (int i = 0; i < 8; ++i)
#pragma unroll
        for (int j = 0; j < 4; ++j) o[i][j] = 0.0f;
    float l0 = 0.0f, l1 = 0.0f;

    const int qrow0 = qt * 128 + w * 16 + (lane >> 2);
    const uint32_t* mb0 = g_Mb + ((size_t)b * S_LEN + qrow0) * (S_LEN / 32);
    const uint32_t* mb1 = mb0 + 8 * (S_LEN / 32);

    const int NKT = S_LEN / 64;
    for (int kt = 0; kt < NKT; ++kt) {
        const int cur = kt & 1;
        if (kt + 1 < NKT) {
            copy_kv(kt + 1, 1 - cur);
            CP_COMMIT();
            CP_WAIT(1);
        } else {
            CP_WAIT(0);
        }
        __syncthreads();

        const uint2 mu0 = *(const uint2*)(mb0 + 2 * kt);
        const uint2 mu1 = *(const uint2*)(mb1 + 2 * kt);

        const uint32_t st = sb + (uint32_t)(cur * STAGE_B);

        // ---- S = Qh Kh^T (Q pre-scaled by SC) ----
        float s[8][4];
#pragma unroll
        for (int i = 0; i < 8; ++i)
#pragma unroll
            for (int j = 0; j < 4; ++j) s[i][j] = 0.0f;

#pragma unroll
        for (int kc2 = 0; kc2 < 2; ++kc2) {
#pragma unroll
            for (int nj = 0; nj < 8; ++nj) {
                uint32_t bh[4];
                uint32_t ad = st + (uint32_t)((nj * 8 + (lane & 7)) * AST
                                  + kc2 * 32 + (lane >> 3) * 8) * 2;
                ldsm_x4(bh, ad);
                mma16816(s[nj], qh[2 * kc2],     bh);
                mma16816(s[nj], qh[2 * kc2 + 1], bh + 2);
            }
        }

        // ---- mask + exp2 + local row sums ----
        float rs0 = 0.0f, rs1 = 0.0f;
        if ((mu0.x & mu0.y & mu1.x & mu1.y) == 0xffffffffu) {
#pragma unroll
            for (int nj = 0; nj < 8; ++nj) {
                s[nj][0] = fexp2(s[nj][0]);
                s[nj][1] = fexp2(s[nj][1]);
                s[nj][2] = fexp2(s[nj][2]);
                s[nj][3] = fexp2(s[nj][3]);
                rs0 += s[nj][0] + s[nj][1];
                rs1 += s[nj][2] + s[nj][3];
            }
        } else {
#pragma unroll
            for (int nj = 0; nj < 8; ++nj) {
                const uint32_t w0 = (nj < 4) ? mu0.x : mu0.y;
                const uint32_t w1 = (nj < 4) ? mu1.x : mu1.y;
                const int bit = (nj & 3) * 8 + (lane & 3) * 2;
                s[nj][0] = ((w0 >> bit) & 1u)       ? s[nj][0] : -1e9f;
                s[nj][1] = ((w0 >> (bit + 1)) & 1u) ? s[nj][1] : -1e9f;
                s[nj][2] = ((w1 >> bit) & 1u)       ? s[nj][2] : -1e9f;
                s[nj][3] = ((w1 >> (bit + 1)) & 1u) ? s[nj][3] : -1e9f;
                s[nj][0] = fexp2(s[nj][0]);
                s[nj][1] = fexp2(s[nj][1]);
                s[nj][2] = fexp2(s[nj][2]);
                s[nj][3] = fexp2(s[nj][3]);
                rs0 += s[nj][0] + s[nj][1];
                rs1 += s[nj][2] + s[nj][3];
            }
        }
        l0 += rs0;
        l1 += rs1;

        // ---- pack ALL of P to fp16 hi/lo ----
        uint32_t ph[16], pl[16];
#pragma unroll
        for (int nj = 0; nj < 8; ++nj) {
            ph[nj * 2]     = pack_split(s[nj][0], s[nj][1], pl[nj * 2]);
            ph[nj * 2 + 1] = pack_split(s[nj][2], s[nj][3], pl[nj * 2 + 1]);
        }

        // ---- O += P V (PhVh + PlVh) ----
#pragma unroll
        for (int kc2 = 0; kc2 < 2; ++kc2) {
            const uint32_t* phA = ph + kc2 * 8;
            const uint32_t* plA = pl + kc2 * 8;
#pragma unroll
            for (int nj2 = 0; nj2 < 8; ++nj2) {
                uint32_t vh[4];
                uint32_t ad = st + KV_TILE_B
                    + (uint32_t)((kc2 * 32 + lane) * AST + nj2 * 8) * 2;
                ldsm_x4t(vh, ad);
                mma16816(o[nj2], phA,     vh);
                mma16816(o[nj2], phA + 4, vh + 2);
                mma16816(o[nj2], plA,     vh);
                mma16816(o[nj2], plA + 4, vh + 2);
            }
        }
        __syncthreads();
    }

    // ---- reduce row sums once, normalize, write ctx fp16 ----
    l0 += __shfl_xor_sync(0xffffffffu, l0, 1);
    l0 += __shfl_xor_sync(0xffffffffu, l0, 2);
    l1 += __shfl_xor_sync(0xffffffffu, l1, 1);
    l1 += __shfl_xor_sync(0xffffffffu, l1, 2);
    const float inv0 = 1.0f / l0;
    const float inv1 = 1.0f / l1;
    const size_t base0 = ((size_t)b * S_LEN + qrow0) * DMODEL
                         + h * HDK + (lane & 3) * 2;
    const size_t base1 = base0 + (size_t)8 * DMODEL;
#pragma unroll
    for (int nj2 = 0; nj2 < 8; ++nj2) {
        __half2 h0 = __floats2half2_rn(o[nj2][0] * inv0, o[nj2][1] * inv0);
        __half2 h1 = __floats2half2_rn(o[nj2][2] * inv1, o[nj2][3] * inv1);
        *(__half2*)(g_Ah + base0 + nj2 * 8) = h0;
        *(__half2*)(g_Ah + base1 + nj2 * 8) = h1;
    }
}

// ---------------- launch ----------------------------------------------------
extern "C" void kernel_launch(void* const* d_in, const int* in_sizes, int n_in,
                              void* d_out, int out_size)
{
    (void)in_sizes; (void)n_in; (void)out_size;
    const float* q  = (const float*)d_in[0];
    const float* k  = (const float*)d_in[1];
    const float* v  = (const float*)d_in[2];
    const int*   mk = (const int*)  d_in[3];
    const float* Wq = (const float*)d_in[4];
    const float* bq = (const float*)d_in[5];
    const float* Wk = (const float*)d_in[6];
    const float* bk = (const float*)d_in[7];
    const float* Wv = (const float*)d_in[8];
    const float* bv = (const float*)d_in[9];
    const float* Wo = (const float*)d_in[10];
    const float* bo = (const float*)d_in[11];
    float* out = (float*)d_out;

    __half *pAh, *pPh, *pWh;
    uint32_t* pMb;
    cudaGetSymbolAddress((void**)&pAh, g_Ah);
    cudaGetSymbolAddress((void**)&pPh, g_Ph);
    cudaGetSymbolAddress((void**)&pWh, g_Wh);
    cudaGetSymbolAddress((void**)&pMb, g_Mb);

    cudaFuncSetAttribute(gemm_mma<0>, cudaFuncAttributeMaxDynamicSharedMemorySize, GM_SMEM);
    cudaFuncSetAttribute(gemm_mma<1>, cudaFuncAttributeMaxDynamicSharedMemorySize, GM_SMEM);
    cudaFuncSetAttribute(attn_mma,    cudaFuncAttributeMaxDynamicSharedMemorySize, ATT_SMEM);

    // fused prep: fp16 convert of q/k/v (y=0..2), weights (y=3), mask (y=4)
    prep<<<dim3(1024, 5), 256>>>(q, k, v, Wq, Wk, Wv, Wo, mk, pAh, pWh, pMb);
    // fused Q/K/V projections (1-pass fp16; Q pre-scaled by SC)
    gemm_mma<1><<<dim3(8, 64, 3), 256, GM_SMEM>>>(pAh, pWh,
                                                  bq, bk, bv, nullptr, pPh);
    // attention (S 1-pass, PV 2-pass; writes ctx fp16 into g_Ah slot 0)
    attn_mma<<<dim3(NH, S_LEN / 128, BATCH), 256, ATT_SMEM>>>();
    // output projection (1-pass fp16; weight slot 3)
    gemm_mma<0><<<dim3(8, 64, 1), 256, GM_SMEM>>>(pAh, pWh + 3 * DD,
                                                  bo, bo, bo, out, nullptr);
}